// round 4
// baseline (speedup 1.0000x reference)
#include <cuda_runtime.h>
#include <cuda_bf16.h>
#include <cstdint>

// RnCLoss: N=4096, D=256, scalar fp32 loss.
// loss = -1/(n(n-1)) * sum_{i != k} [ logits[i,k] - log(denom[i,k]) ]
//   logits = (F F^T)/tau ;  denom over label-distance indicator.
//
// Pipeline: convert F->bf16, bitonic label sort, bf16 HMMA GEMM over
// lower-triangle tiles (writes tile + transpose), per-row kernel that walks
// sorted label positions with MONOTONE two-pointer boundaries (one binary
// search per 16-chunk), padded smem (bank-conflict-free), polynomial exp/log
// on the FMA pipe, finalize.

#define NN 4096
#define DD 256

__device__ float g_S[(size_t)NN * NN];            // logits/tau, 64 MB
__device__ __align__(16) __nv_bfloat16 g_Fb[(size_t)NN * DD];
__device__ float g_labels[NN];
__device__ float g_ls[NN];
__device__ int   g_ord[NN];
__device__ float g_partials[NN];

__device__ __forceinline__ float read_epoch(const void* p) {
    int ei = *(const int*)p;
    if (ei >= 0 && ei <= 1000000) return (float)ei;
    return *(const float*)p;
}

// ---- FMA-pipe math (offload MUFU) ------------------------------------------
// exp(x) ~ 1e-7 rel err; valid for |x| < 80 (clamped exponent).
__device__ __forceinline__ float exp_poly(float x) {
    float y = x * 1.44269504089f;
    int   n = __float2int_rn(y);
    float f = y - (float)n;                    // |f| <= 0.5
    float p = 1.54035304e-4f;
    p = fmaf(p, f, 1.33335581e-3f);
    p = fmaf(p, f, 9.61812910e-3f);
    p = fmaf(p, f, 5.55041087e-2f);
    p = fmaf(p, f, 2.40226507e-1f);
    p = fmaf(p, f, 6.93147181e-1f);
    p = fmaf(p, f, 1.0f);
    n = max(-126, min(127, n));
    return __int_as_float((n + 127) << 23) * p;
}
// log(x), cephes-style, ~1-2 ulp for normal positive x.
__device__ __forceinline__ float log_poly(float x) {
    int xi = __float_as_int(x);
    int e  = (xi >> 23) - 127;
    float m = __int_as_float((xi & 0x007FFFFF) | 0x3F800000);   // [1,2)
    if (m > 1.41421356f) { m *= 0.5f; e++; }
    float f = m - 1.0f;                        // [-0.2929, 0.4142]
    float z = f * f;
    float p =  7.0376836292e-2f;
    p = fmaf(p, f, -1.1514610310e-1f);
    p = fmaf(p, f,  1.1676998740e-1f);
    p = fmaf(p, f, -1.2420140846e-1f);
    p = fmaf(p, f,  1.4249322787e-1f);
    p = fmaf(p, f, -1.6668057665e-1f);
    p = fmaf(p, f,  2.0000714765e-1f);
    p = fmaf(p, f, -2.4999993993e-1f);
    p = fmaf(p, f,  3.3333331174e-1f);
    float y = fmaf(z * f, p, -0.5f * z) + f;
    return fmaf((float)e, 0.69314718056f, y);
}

// ---------------- kernel 0: fp32 -> bf16 convert -----------------------------
__global__ void __launch_bounds__(256) convert_kernel(const float* __restrict__ F) {
    int base = (blockIdx.x * 256 + threadIdx.x) * 8;
    float4 v0 = *(const float4*)(F + base);
    float4 v1 = *(const float4*)(F + base + 4);
    __nv_bfloat162 b0 = __floats2bfloat162_rn(v0.x, v0.y);
    __nv_bfloat162 b1 = __floats2bfloat162_rn(v0.z, v0.w);
    __nv_bfloat162 b2 = __floats2bfloat162_rn(v1.x, v1.y);
    __nv_bfloat162 b3 = __floats2bfloat162_rn(v1.z, v1.w);
    uint4 packed;
    packed.x = *(uint32_t*)&b0; packed.y = *(uint32_t*)&b1;
    packed.z = *(uint32_t*)&b2; packed.w = *(uint32_t*)&b3;
    *(uint4*)(g_Fb + base) = packed;
}

// ---------------- kernel 1: labels + bitonic sort ----------------------------
__global__ void __launch_bounds__(1024) sort_kernel(
    const float* __restrict__ origin,
    const float* __restrict__ mean,
    const float* __restrict__ stdv)
{
    __shared__ float key[NN];
    __shared__ int   val[NN];
    int t = threadIdx.x;
    float mu = mean[0];
    float sd = stdv[0] + 1e-8f;
    for (int i = t; i < NN; i += 1024) {
        float l = (origin[i] - mu) / sd;
        key[i] = l; val[i] = i;
        g_labels[i] = l;
    }
    __syncthreads();
    for (int k = 2; k <= NN; k <<= 1) {
        for (int j = k >> 1; j > 0; j >>= 1) {
            for (int i = t; i < NN; i += 1024) {
                int ixj = i ^ j;
                if (ixj > i) {
                    bool up = ((i & k) == 0);
                    float a = key[i], b = key[ixj];
                    if ((a > b) == up) {
                        key[i] = b; key[ixj] = a;
                        int tv = val[i]; val[i] = val[ixj]; val[ixj] = tv;
                    }
                }
            }
            __syncthreads();
        }
    }
    for (int i = t; i < NN; i += 1024) { g_ls[i] = key[i]; g_ord[i] = val[i]; }
}

// ---------------- kernel 2: bf16 HMMA GEMM (lower-triangle tiles) ------------
#define ASTRIDE 40

__device__ __forceinline__ uint32_t sptr(const void* p) {
    return (uint32_t)__cvta_generic_to_shared(p);
}
__device__ __forceinline__ void ldsm4(uint32_t& r0, uint32_t& r1, uint32_t& r2,
                                      uint32_t& r3, uint32_t addr) {
    asm volatile("ldmatrix.sync.aligned.m8n8.x4.shared.b16 {%0,%1,%2,%3}, [%4];"
                 : "=r"(r0), "=r"(r1), "=r"(r2), "=r"(r3) : "r"(addr));
}
__device__ __forceinline__ void mma16816(float* c, uint32_t a0, uint32_t a1,
                                         uint32_t a2, uint32_t a3,
                                         uint32_t b0, uint32_t b1) {
    asm volatile(
        "mma.sync.aligned.m16n8k16.row.col.f32.bf16.bf16.f32 "
        "{%0,%1,%2,%3}, {%4,%5,%6,%7}, {%8,%9}, {%0,%1,%2,%3};"
        : "+f"(c[0]), "+f"(c[1]), "+f"(c[2]), "+f"(c[3])
        : "r"(a0), "r"(a1), "r"(a2), "r"(a3), "r"(b0), "r"(b1));
}

__global__ void __launch_bounds__(256) gemm_kernel(const void* __restrict__ epoch_ptr)
{
    __shared__ __align__(16) unsigned char smem_buf[2 * 128 * ASTRIDE * 2];
    __nv_bfloat16* sA = (__nv_bfloat16*)smem_buf;
    __nv_bfloat16* sB = sA + 128 * ASTRIDE;
    float* tr = (float*)smem_buf;

    int b = blockIdx.x;
    int bi = (int)((sqrtf(8.0f * b + 1.0f) - 1.0f) * 0.5f);
    while ((bi + 1) * (bi + 2) / 2 <= b) bi++;
    while (bi * (bi + 1) / 2 > b) bi--;
    int bj = b - bi * (bi + 1) / 2;
    int i0 = bi * 128, j0 = bj * 128;

    int t = threadIdx.x;
    int lane = t & 31, w = t >> 5;
    int warp_m = w & 1;
    int warp_n = w >> 1;

    float epoch = read_epoch(epoch_ptr);
    float itau = 1.0f / (1.0f - 0.9f * epoch / 100.0f);

    float acc[4][4][4];
#pragma unroll
    for (int mb = 0; mb < 4; mb++)
#pragma unroll
        for (int nb = 0; nb < 4; nb++)
#pragma unroll
            for (int r = 0; r < 4; r++) acc[mb][nb][r] = 0.0f;

    for (int kk = 0; kk < DD; kk += 32) {
#pragma unroll
        for (int s = 0; s < 2; s++) {
            int idx = t + s * 256;
            int r = idx >> 2, cg = idx & 3;
            uint4 va = *(const uint4*)(g_Fb + (size_t)(i0 + r) * DD + kk + cg * 8);
            *(uint4*)(sA + r * ASTRIDE + cg * 8) = va;
            uint4 vb = *(const uint4*)(g_Fb + (size_t)(j0 + r) * DD + kk + cg * 8);
            *(uint4*)(sB + r * ASTRIDE + cg * 8) = vb;
        }
        __syncthreads();

#pragma unroll
        for (int ks = 0; ks < 2; ks++) {
            int kb = ks * 16;
            uint32_t af[4][4];
#pragma unroll
            for (int mb = 0; mb < 4; mb++) {
                int row = warp_m * 64 + mb * 16 + (lane & 7) + ((lane >> 3) & 1) * 8;
                int col = kb + (lane >> 4) * 8;
                ldsm4(af[mb][0], af[mb][1], af[mb][2], af[mb][3],
                      sptr(sA + row * ASTRIDE + col));
            }
            uint32_t bf[2][4];
#pragma unroll
            for (int hb = 0; hb < 2; hb++) {
                int n = warp_n * 32 + hb * 16 + ((lane >> 4) & 1) * 8 + (lane & 7);
                int col = kb + ((lane >> 3) & 1) * 8;
                ldsm4(bf[hb][0], bf[hb][1], bf[hb][2], bf[hb][3],
                      sptr(sB + n * ASTRIDE + col));
            }
#pragma unroll
            for (int mb = 0; mb < 4; mb++)
#pragma unroll
                for (int nb = 0; nb < 4; nb++) {
                    int hb = nb >> 1, pr = nb & 1;
                    mma16816(acc[mb][nb], af[mb][0], af[mb][1], af[mb][2], af[mb][3],
                             bf[hb][pr * 2], bf[hb][pr * 2 + 1]);
                }
        }
        __syncthreads();
    }

#pragma unroll
    for (int mb = 0; mb < 4; mb++)
#pragma unroll
        for (int nb = 0; nb < 4; nb++)
#pragma unroll
            for (int r = 0; r < 4; r++) acc[mb][nb][r] *= itau;

#pragma unroll
    for (int mb = 0; mb < 4; mb++)
#pragma unroll
        for (int nb = 0; nb < 4; nb++) {
            int row = warp_m * 64 + mb * 16 + (lane >> 2);
            int col = warp_n * 32 + nb * 8 + (lane & 3) * 2;
            float2 v01 = make_float2(acc[mb][nb][0], acc[mb][nb][1]);
            float2 v23 = make_float2(acc[mb][nb][2], acc[mb][nb][3]);
            *(float2*)&g_S[(size_t)(i0 + row) * NN + j0 + col] = v01;
            *(float2*)&g_S[(size_t)(i0 + row + 8) * NN + j0 + col] = v23;
        }

    if (bi != bj) {
        __syncthreads();
#pragma unroll
        for (int c = 0; c < 4; c++) {
            if (warp_n == c) {
#pragma unroll
                for (int mb = 0; mb < 4; mb++)
#pragma unroll
                    for (int nb = 0; nb < 4; nb++) {
                        int row = warp_m * 64 + mb * 16 + (lane >> 2);
                        int cl = nb * 8 + (lane & 3) * 2;
                        tr[cl * 132 + row]           = acc[mb][nb][0];
                        tr[(cl + 1) * 132 + row]     = acc[mb][nb][1];
                        tr[cl * 132 + row + 8]       = acc[mb][nb][2];
                        tr[(cl + 1) * 132 + row + 8] = acc[mb][nb][3];
                    }
            }
            __syncthreads();
#pragma unroll
            for (int s = 0; s < 4; s++) {
                int q = t + s * 256;
                int cl = q >> 5, c4 = q & 31;
                float4 v = *(float4*)&tr[cl * 132 + c4 * 4];
                *(float4*)&g_S[(size_t)(j0 + c * 32 + cl) * NN + i0 + c4 * 4] = v;
            }
            __syncthreads();
        }
    }
}

// ---------------- kernel 3: per-row denom + partial loss ---------------------
// Sorted-position iteration with monotone two-pointer boundaries.
// Padded smem layout: IDX(m) = m + m/16  (odd thread stride 17 -> no conflicts)
#define ROW_THREADS 256
#define CH 16
#define PADN (NN + NN / 16)            // 4352
#define ROW_SMEM_FLOATS (2 * PADN + 256)
#define IDX(m) ((m) + ((m) >> 4))

__global__ void __launch_bounds__(ROW_THREADS) row_kernel()
{
    extern __shared__ float sm[];
    float* s_ls  = sm;                  // sorted labels, padded
    float* s_p   = sm + PADN;           // scanned exp, padded
    float* s_red = sm + 2 * PADN;
    __shared__ int   sh_pi;
    __shared__ float sh_self;

    const int i = blockIdx.x;
    const int t = threadIdx.x;
    const float* Srow = &g_S[(size_t)i * NN];

    // gather labels + exp(logits) in sorted order; rowsum folded in (sum is
    // permutation-invariant).
    float rs = 0.0f;
    for (int m = t; m < NN; m += ROW_THREADS) {
        s_ls[IDX(m)] = g_ls[m];
        int src = g_ord[m];
        float v = Srow[src];
        if (src == i) { sh_pi = m; sh_self = v; }
        rs += v;
        s_p[IDX(m)] = exp_poly(v);
    }
    __syncthreads();

    // inclusive scan of s_p (conflict-free thanks to padding: base = 17*t)
    const int base = t * (CH + 1);      // IDX(t*CH)
    float run = 0.0f;
#pragma unroll
    for (int q = 0; q < CH; q++) { run += s_p[base + q]; s_p[base + q] = run; }
    int lane = t & 31, warp = t >> 5;
    float v = run;
#pragma unroll
    for (int d = 1; d < 32; d <<= 1) {
        float u = __shfl_up_sync(0xFFFFFFFFu, v, d);
        if (lane >= d) v += u;
    }
    if (lane == 31) s_red[warp] = v;
    __syncthreads();
    if (warp == 0 && lane < 8) {
        float wv = s_red[lane];
#pragma unroll
        for (int d = 1; d < 8; d <<= 1) {
            float u = __shfl_up_sync(0xFFu, wv, d);
            if (lane >= d) wv += u;
        }
        s_red[lane] = wv;
    }
    __syncthreads();
    float off = (warp > 0 ? s_red[warp - 1] : 0.0f) + (v - run);
#pragma unroll
    for (int q = 0; q < CH; q++) s_p[base + q] += off;
    __syncthreads();

    const float T  = s_p[IDX(NN - 1)];
    const int   pi = sh_pi;
    const float li = s_ls[IDX(pi)];
    const float e_self = exp_poly(sh_self);
    const float log_tie = log_poly(T - e_self);

    const int c0 = t * CH, c1 = c0 + CH;
    float logsum = 0.0f;

    // ---- LEFT part: q in [c0, min(c1, pi)), descending (|dq| increasing) ----
    int ql_end = min(c1, pi);
    if (c0 < ql_end) {
        int q = ql_end - 1;
        // init opposite pointer: a2 = first m in [pi+1, NN) with d(m) >= -dq
        int a2;
        {
            float tp = -(s_ls[base + (q - c0)] - li);
            int lo = pi + 1, hi = NN;
            while (lo < hi) {
                int m = (lo + hi) >> 1;
                if ((s_ls[IDX(m)] - li) < tp) lo = m + 1; else hi = m;
            }
            a2 = lo;
        }
        for (; q >= c0; q--) {
            float dq = s_ls[base + (q - c0)] - li;     // <= 0
            if (dq == 0.0f) { logsum += log_tie; continue; }
            float tp = -dq;
            while (a2 < NN && (s_ls[IDX(a2)] - li) < tp) a2++;
            int lo = q + 1;                             // tie-forward (rare)
            while (lo < NN && (s_ls[IDX(lo)] - li) <= dq) lo++;
            float left  = s_p[IDX(lo - 1)];
            float right = T - s_p[IDX(a2 - 1)];         // a2 >= pi+1 >= 1
            logsum += log_poly(left + right);
        }
    }

    // ---- RIGHT part: q in [max(c0, pi+1), c1), ascending (dq increasing) ----
    int qr_start = max(c0, pi + 1);
    if (qr_start < c1) {
        int q = qr_start;
        // init opposite pointer: a = count of m in [0, pi) with d(m) <= -dq
        int a;
        {
            float nt = -(s_ls[base + (q - c0)] - li);
            int lo = 0, hi = pi;
            while (lo < hi) {
                int m = (lo + hi) >> 1;
                if ((s_ls[IDX(m)] - li) <= nt) lo = m + 1; else hi = m;
            }
            a = lo;
        }
        for (; q < c1; q++) {
            float dq = s_ls[base + (q - c0)] - li;     // >= 0
            if (dq == 0.0f) { logsum += log_tie; continue; }
            float nt = -dq;
            while (a > 0 && (s_ls[IDX(a - 1)] - li) > nt) a--;
            int lo2 = q;                                // tie-back (rare)
            while (lo2 > 0 && (s_ls[IDX(lo2 - 1)] - li) >= dq) lo2--;
            float left  = a ? s_p[IDX(a - 1)] : 0.0f;
            float right = T - s_p[IDX(lo2 - 1)];        // lo2 >= pi+1 >= 1
            logsum += log_poly(left + right);
        }
    }

    // reduce rs and logsum
    __syncthreads();
    s_red[t] = rs;
    __syncthreads();
    for (int s = ROW_THREADS / 2; s > 0; s >>= 1) {
        if (t < s) s_red[t] += s_red[t + s];
        __syncthreads();
    }
    float rowsum = s_red[0];
    __syncthreads();
    s_red[t] = logsum;
    __syncthreads();
    for (int s = ROW_THREADS / 2; s > 0; s >>= 1) {
        if (t < s) s_red[t] += s_red[t + s];
        __syncthreads();
    }
    if (t == 0) g_partials[i] = (rowsum - sh_self) - s_red[0];
}

// ---------------- kernel 4: finalize ----------------------------------------
__global__ void __launch_bounds__(256) finalize_kernel(float* __restrict__ out)
{
    __shared__ double sh[256];
    int t = threadIdx.x;
    double a = 0.0;
    for (int i = t; i < NN; i += 256) a += (double)g_partials[i];
    sh[t] = a;
    __syncthreads();
    for (int s = 128; s > 0; s >>= 1) {
        if (t < s) sh[t] += sh[t + s];
        __syncthreads();
    }
    if (t == 0) out[0] = (float)(-sh[0] / ((double)NN * (double)(NN - 1)));
}

// ---------------- launch -----------------------------------------------------
extern "C" void kernel_launch(void* const* d_in, const int* in_sizes, int n_in,
                              void* d_out, int out_size)
{
    const float* F      = (const float*)d_in[0];
    const float* origin = (const float*)d_in[1];
    const float* mean   = (const float*)d_in[2];
    const float* stdv   = (const float*)d_in[3];
    const void*  epoch  = d_in[4];

    convert_kernel<<<(NN * DD) / (256 * 8), 256>>>(F);
    sort_kernel<<<1, 1024>>>(origin, mean, stdv);

    gemm_kernel<<<32 * 33 / 2, 256>>>(epoch);

    size_t smem = ROW_SMEM_FLOATS * sizeof(float);
    cudaFuncSetAttribute(row_kernel, cudaFuncAttributeMaxDynamicSharedMemorySize, (int)smem);
    row_kernel<<<NN, ROW_THREADS, smem>>>();

    finalize_kernel<<<1, 256>>>((float*)d_out);
}

// round 6
// speedup vs baseline: 1.4972x; 1.4972x over previous
#include <cuda_runtime.h>
#include <cuda_bf16.h>
#include <cstdint>

// RnCLoss: N=4096, D=256, scalar fp32 loss.
// loss = -1/(n(n-1)) * sum_{i != k} [ logits[i,k] - log(denom[i,k]) ]
//   logits = (F F^T)/tau ;  denom over label-distance indicator.
//
// Pipeline: convert F->bf16, bitonic label sort, bf16 HMMA GEMM over
// lower-triangle tiles (writes tile + transpose), per-row kernel where the
// opposite-side boundary ranks for ALL sorted positions are produced by a
// single lockstep MERGE-PATH pass (1 diag search + 16 fixed steps / thread),
// then a lockstep lookup loop. Padded smem (conflict-free), finalize.

#define NN 4096
#define DD 256

__device__ float g_S[(size_t)NN * NN];            // logits/tau, 64 MB
__device__ __align__(16) __nv_bfloat16 g_Fb[(size_t)NN * DD];
__device__ float g_labels[NN];
__device__ float g_ls[NN];
__device__ int   g_ord[NN];
__device__ float g_partials[NN];

__device__ __forceinline__ float read_epoch(const void* p) {
    int ei = *(const int*)p;
    if (ei >= 0 && ei <= 1000000) return (float)ei;
    return *(const float*)p;
}

// ---------------- kernel 0: fp32 -> bf16 convert -----------------------------
__global__ void __launch_bounds__(256) convert_kernel(const float* __restrict__ F) {
    int base = (blockIdx.x * 256 + threadIdx.x) * 8;
    float4 v0 = *(const float4*)(F + base);
    float4 v1 = *(const float4*)(F + base + 4);
    __nv_bfloat162 b0 = __floats2bfloat162_rn(v0.x, v0.y);
    __nv_bfloat162 b1 = __floats2bfloat162_rn(v0.z, v0.w);
    __nv_bfloat162 b2 = __floats2bfloat162_rn(v1.x, v1.y);
    __nv_bfloat162 b3 = __floats2bfloat162_rn(v1.z, v1.w);
    uint4 packed;
    packed.x = *(uint32_t*)&b0; packed.y = *(uint32_t*)&b1;
    packed.z = *(uint32_t*)&b2; packed.w = *(uint32_t*)&b3;
    *(uint4*)(g_Fb + base) = packed;
}

// ---------------- kernel 1: labels + bitonic sort ----------------------------
__global__ void __launch_bounds__(1024) sort_kernel(
    const float* __restrict__ origin,
    const float* __restrict__ mean,
    const float* __restrict__ stdv)
{
    __shared__ float key[NN];
    __shared__ int   val[NN];
    int t = threadIdx.x;
    float mu = mean[0];
    float sd = stdv[0] + 1e-8f;
    for (int i = t; i < NN; i += 1024) {
        float l = (origin[i] - mu) / sd;
        key[i] = l; val[i] = i;
        g_labels[i] = l;
    }
    __syncthreads();
    for (int k = 2; k <= NN; k <<= 1) {
        for (int j = k >> 1; j > 0; j >>= 1) {
            for (int i = t; i < NN; i += 1024) {
                int ixj = i ^ j;
                if (ixj > i) {
                    bool up = ((i & k) == 0);
                    float a = key[i], b = key[ixj];
                    if ((a > b) == up) {
                        key[i] = b; key[ixj] = a;
                        int tv = val[i]; val[i] = val[ixj]; val[ixj] = tv;
                    }
                }
            }
            __syncthreads();
        }
    }
    for (int i = t; i < NN; i += 1024) { g_ls[i] = key[i]; g_ord[i] = val[i]; }
}

// ---------------- kernel 2: bf16 HMMA GEMM (lower-triangle tiles) ------------
#define ASTRIDE 40

__device__ __forceinline__ uint32_t sptr(const void* p) {
    return (uint32_t)__cvta_generic_to_shared(p);
}
__device__ __forceinline__ void ldsm4(uint32_t& r0, uint32_t& r1, uint32_t& r2,
                                      uint32_t& r3, uint32_t addr) {
    asm volatile("ldmatrix.sync.aligned.m8n8.x4.shared.b16 {%0,%1,%2,%3}, [%4];"
                 : "=r"(r0), "=r"(r1), "=r"(r2), "=r"(r3) : "r"(addr));
}
__device__ __forceinline__ void mma16816(float* c, uint32_t a0, uint32_t a1,
                                         uint32_t a2, uint32_t a3,
                                         uint32_t b0, uint32_t b1) {
    asm volatile(
        "mma.sync.aligned.m16n8k16.row.col.f32.bf16.bf16.f32 "
        "{%0,%1,%2,%3}, {%4,%5,%6,%7}, {%8,%9}, {%0,%1,%2,%3};"
        : "+f"(c[0]), "+f"(c[1]), "+f"(c[2]), "+f"(c[3])
        : "r"(a0), "r"(a1), "r"(a2), "r"(a3), "r"(b0), "r"(b1));
}

__global__ void __launch_bounds__(256) gemm_kernel(const void* __restrict__ epoch_ptr)
{
    __shared__ __align__(16) unsigned char smem_buf[2 * 128 * ASTRIDE * 2];
    __nv_bfloat16* sA = (__nv_bfloat16*)smem_buf;
    __nv_bfloat16* sB = sA + 128 * ASTRIDE;
    float* tr = (float*)smem_buf;

    int b = blockIdx.x;
    int bi = (int)((sqrtf(8.0f * b + 1.0f) - 1.0f) * 0.5f);
    while ((bi + 1) * (bi + 2) / 2 <= b) bi++;
    while (bi * (bi + 1) / 2 > b) bi--;
    int bj = b - bi * (bi + 1) / 2;
    int i0 = bi * 128, j0 = bj * 128;

    int t = threadIdx.x;
    int lane = t & 31, w = t >> 5;
    int warp_m = w & 1;
    int warp_n = w >> 1;

    float epoch = read_epoch(epoch_ptr);
    float itau = 1.0f / (1.0f - 0.9f * epoch / 100.0f);

    float acc[4][4][4];
#pragma unroll
    for (int mb = 0; mb < 4; mb++)
#pragma unroll
        for (int nb = 0; nb < 4; nb++)
#pragma unroll
            for (int r = 0; r < 4; r++) acc[mb][nb][r] = 0.0f;

    for (int kk = 0; kk < DD; kk += 32) {
#pragma unroll
        for (int s = 0; s < 2; s++) {
            int idx = t + s * 256;
            int r = idx >> 2, cg = idx & 3;
            uint4 va = *(const uint4*)(g_Fb + (size_t)(i0 + r) * DD + kk + cg * 8);
            *(uint4*)(sA + r * ASTRIDE + cg * 8) = va;
            uint4 vb = *(const uint4*)(g_Fb + (size_t)(j0 + r) * DD + kk + cg * 8);
            *(uint4*)(sB + r * ASTRIDE + cg * 8) = vb;
        }
        __syncthreads();

#pragma unroll
        for (int ks = 0; ks < 2; ks++) {
            int kb = ks * 16;
            uint32_t af[4][4];
#pragma unroll
            for (int mb = 0; mb < 4; mb++) {
                int row = warp_m * 64 + mb * 16 + (lane & 7) + ((lane >> 3) & 1) * 8;
                int col = kb + (lane >> 4) * 8;
                ldsm4(af[mb][0], af[mb][1], af[mb][2], af[mb][3],
                      sptr(sA + row * ASTRIDE + col));
            }
            uint32_t bf[2][4];
#pragma unroll
            for (int hb = 0; hb < 2; hb++) {
                int n = warp_n * 32 + hb * 16 + ((lane >> 4) & 1) * 8 + (lane & 7);
                int col = kb + ((lane >> 3) & 1) * 8;
                ldsm4(bf[hb][0], bf[hb][1], bf[hb][2], bf[hb][3],
                      sptr(sB + n * ASTRIDE + col));
            }
#pragma unroll
            for (int mb = 0; mb < 4; mb++)
#pragma unroll
                for (int nb = 0; nb < 4; nb++) {
                    int hb = nb >> 1, pr = nb & 1;
                    mma16816(acc[mb][nb], af[mb][0], af[mb][1], af[mb][2], af[mb][3],
                             bf[hb][pr * 2], bf[hb][pr * 2 + 1]);
                }
        }
        __syncthreads();
    }

#pragma unroll
    for (int mb = 0; mb < 4; mb++)
#pragma unroll
        for (int nb = 0; nb < 4; nb++)
#pragma unroll
            for (int r = 0; r < 4; r++) acc[mb][nb][r] *= itau;

#pragma unroll
    for (int mb = 0; mb < 4; mb++)
#pragma unroll
        for (int nb = 0; nb < 4; nb++) {
            int row = warp_m * 64 + mb * 16 + (lane >> 2);
            int col = warp_n * 32 + nb * 8 + (lane & 3) * 2;
            float2 v01 = make_float2(acc[mb][nb][0], acc[mb][nb][1]);
            float2 v23 = make_float2(acc[mb][nb][2], acc[mb][nb][3]);
            *(float2*)&g_S[(size_t)(i0 + row) * NN + j0 + col] = v01;
            *(float2*)&g_S[(size_t)(i0 + row + 8) * NN + j0 + col] = v23;
        }

    if (bi != bj) {
        __syncthreads();
#pragma unroll
        for (int c = 0; c < 4; c++) {
            if (warp_n == c) {
#pragma unroll
                for (int mb = 0; mb < 4; mb++)
#pragma unroll
                    for (int nb = 0; nb < 4; nb++) {
                        int row = warp_m * 64 + mb * 16 + (lane >> 2);
                        int cl = nb * 8 + (lane & 3) * 2;
                        tr[cl * 132 + row]           = acc[mb][nb][0];
                        tr[(cl + 1) * 132 + row]     = acc[mb][nb][1];
                        tr[cl * 132 + row + 8]       = acc[mb][nb][2];
                        tr[(cl + 1) * 132 + row + 8] = acc[mb][nb][3];
                    }
            }
            __syncthreads();
#pragma unroll
            for (int s = 0; s < 4; s++) {
                int q = t + s * 256;
                int cl = q >> 5, c4 = q & 31;
                float4 v = *(float4*)&tr[cl * 132 + c4 * 4];
                *(float4*)&g_S[(size_t)(j0 + c * 32 + cl) * NN + i0 + c4 * 4] = v;
            }
            __syncthreads();
        }
    }
}

// ---------------- kernel 3: per-row denom + partial loss ---------------------
// d[m] = fl(ls[m] - li), sorted. L = {d<0} = [0,z0), Z = {d==0}, R = (z1..NN).
// X[s] = -d[z0-1-s] (ascending), Y[r] = d[z1+r] (ascending).
// One merge-path pass gives, lockstep:
//   q in L: rnk[q] = #{Y <  X}  -> a2 = z1 + rnk  (exact)
//   q in R: rnk[q] = #{X <= Y}  -> a  = z0 - rnk  (off only on exact fp ties;
//            bounded, cannot zero the denom; ~1e-7 loss effect)
#define ROW_THREADS 256
#define CH 16
#define PADN (NN + NN / 16)            // 4352
#define ROW_SMEM_FLOATS (3 * PADN + 256)
#define IDX(m) ((m) + ((m) >> 4))

__global__ void __launch_bounds__(ROW_THREADS) row_kernel()
{
    extern __shared__ float sm[];
    float* s_d   = sm;                  // sorted label diffs, padded
    float* s_p   = sm + PADN;           // scanned exp, padded
    int*   s_rnk = (int*)(sm + 2 * PADN);
    float* s_red = sm + 3 * PADN;
    __shared__ int   sh_pi;
    __shared__ float sh_self;

    const int i = blockIdx.x;
    const int t = threadIdx.x;
    const float* Srow = &g_S[(size_t)i * NN];
    const float li = g_labels[i];

    // gather diffs + exp(logits) in sorted order; rowsum folded in.
    float rs = 0.0f;
    for (int m = t; m < NN; m += ROW_THREADS) {
        s_d[IDX(m)] = g_ls[m] - li;
        int src = g_ord[m];
        float v = Srow[src];
        if (src == i) { sh_pi = m; sh_self = v; }
        rs += v;
        s_p[IDX(m)] = __expf(v);
    }
    __syncthreads();

    // inclusive scan of s_p (conflict-free: base stride 17)
    const int base = t * (CH + 1);      // IDX(t*CH)
    float run = 0.0f;
#pragma unroll
    for (int q = 0; q < CH; q++) { run += s_p[base + q]; s_p[base + q] = run; }
    int lane = t & 31, warp = t >> 5;
    float v = run;
#pragma unroll
    for (int d = 1; d < 32; d <<= 1) {
        float u = __shfl_up_sync(0xFFFFFFFFu, v, d);
        if (lane >= d) v += u;
    }
    if (lane == 31) s_red[warp] = v;
    __syncthreads();
    if (warp == 0 && lane < 8) {
        float wv = s_red[lane];
#pragma unroll
        for (int d = 1; d < 8; d <<= 1) {
            float u = __shfl_up_sync(0xFFu, wv, d);
            if (lane >= d) wv += u;
        }
        s_red[lane] = wv;
    }
    __syncthreads();
    float off = (warp > 0 ? s_red[warp - 1] : 0.0f) + (v - run);
#pragma unroll
    for (int q = 0; q < CH; q++) s_p[base + q] += off;
    __syncthreads();

    const float T  = s_p[IDX(NN - 1)];
    const int   pi = sh_pi;

    // z0 = first m with d >= 0 ; z1 = first m with d > 0 (broadcast searches)
    int z0, z1;
    {
        int lo = 0, hi = NN;
        while (lo < hi) { int m = (lo + hi) >> 1; if (s_d[IDX(m)] < 0.0f) lo = m + 1; else hi = m; }
        z0 = lo;
        lo = 0; hi = NN;
        while (lo < hi) { int m = (lo + hi) >> 1; if (s_d[IDX(m)] <= 0.0f) lo = m + 1; else hi = m; }
        z1 = lo;
    }

    // ---- merge-path: ranks for all positions, 16 lockstep steps/thread ----
    const int nx = z0, ny = NN - z1, n = nx + ny;
    {
        int k = t * CH;
        if (k < n) {
            int lo = max(0, k - ny), hi = min(k, nx);
            while (lo < hi) {
                int mid = (lo + hi) >> 1;
                int sy = k - mid;
                bool adv = (sy > 0) && (mid < nx) &&
                           (s_d[IDX(z1 + sy - 1)] >= -s_d[IDX(z0 - 1 - mid)]);
                if (adv) lo = mid + 1; else hi = mid;
            }
            int sx = lo, sy = k - lo;
            int lim = min(CH, n - k);
            for (int g = 0; g < lim; g++) {
                bool takeX;
                if (sy >= ny)      takeX = true;
                else if (sx >= nx) takeX = false;
                else takeX = (-s_d[IDX(z0 - 1 - sx)] <= s_d[IDX(z1 + sy)]);
                if (takeX) { s_rnk[IDX(z0 - 1 - sx)] = sy; sx++; }
                else       { s_rnk[IDX(z1 + sy)] = sx; sy++; }
            }
        }
    }
    __syncthreads();

    // ---- main loop: lockstep lookups ----
    const float e_self  = __expf(sh_self);
    const float log_tie = __logf(T - e_self);
    const int c0 = t * CH;
    float logsum = 0.0f;

#pragma unroll 4
    for (int j = 0; j < CH; j++) {
        int q = c0 + j;
        if (q == pi) continue;
        float dq = s_d[base + j];
        if (dq == 0.0f) { logsum += log_tie; continue; }
        float denom;
        if (dq < 0.0f) {
            int lo = q + 1;                            // tie-walk (rare)
            while (lo < NN && s_d[IDX(lo)] <= dq) lo++;
            int a2 = z1 + s_rnk[base + j];
            denom = s_p[IDX(lo - 1)] + (T - s_p[IDX(a2 - 1)]);
        } else {
            int r = q;                                 // tie-walk (rare)
            while (r > 0 && s_d[IDX(r - 1)] >= dq) r--;
            int a = z0 - s_rnk[base + j];
            float left = (a > 0) ? s_p[IDX(a - 1)] : 0.0f;
            denom = left + (T - s_p[IDX(r - 1)]);
        }
        logsum += __logf(denom);
    }

    // reduce rs and logsum
    __syncthreads();
    s_red[t] = rs;
    __syncthreads();
    for (int s = ROW_THREADS / 2; s > 0; s >>= 1) {
        if (t < s) s_red[t] += s_red[t + s];
        __syncthreads();
    }
    float rowsum = s_red[0];
    __syncthreads();
    s_red[t] = logsum;
    __syncthreads();
    for (int s = ROW_THREADS / 2; s > 0; s >>= 1) {
        if (t < s) s_red[t] += s_red[t + s];
        __syncthreads();
    }
    if (t == 0) g_partials[i] = (rowsum - sh_self) - s_red[0];
}

// ---------------- kernel 4: finalize ----------------------------------------
__global__ void __launch_bounds__(256) finalize_kernel(float* __restrict__ out)
{
    __shared__ double sh[256];
    int t = threadIdx.x;
    double a = 0.0;
    for (int i = t; i < NN; i += 256) a += (double)g_partials[i];
    sh[t] = a;
    __syncthreads();
    for (int s = 128; s > 0; s >>= 1) {
        if (t < s) sh[t] += sh[t + s];
        __syncthreads();
    }
    if (t == 0) out[0] = (float)(-sh[0] / ((double)NN * (double)(NN - 1)));
}

// ---------------- launch -----------------------------------------------------
extern "C" void kernel_launch(void* const* d_in, const int* in_sizes, int n_in,
                              void* d_out, int out_size)
{
    const float* F      = (const float*)d_in[0];
    const float* origin = (const float*)d_in[1];
    const float* mean   = (const float*)d_in[2];
    const float* stdv   = (const float*)d_in[3];
    const void*  epoch  = d_in[4];

    convert_kernel<<<(NN * DD) / (256 * 8), 256>>>(F);
    sort_kernel<<<1, 1024>>>(origin, mean, stdv);

    gemm_kernel<<<32 * 33 / 2, 256>>>(epoch);

    size_t smem = ROW_SMEM_FLOATS * sizeof(float);
    cudaFuncSetAttribute(row_kernel, cudaFuncAttributeMaxDynamicSharedMemorySize, (int)smem);
    row_kernel<<<NN, ROW_THREADS, smem>>>();

    finalize_kernel<<<1, 256>>>((float*)d_out);
}

// round 7
// speedup vs baseline: 2.1603x; 1.4429x over previous
#include <cuda_runtime.h>
#include <cuda_bf16.h>
#include <cstdint>

// RnCLoss: N=4096, D=256, scalar fp32 loss.
// loss = -1/(n(n-1)) * sum_{i != k} [ logits[i,k] - log(denom[i,k]) ]
//
// This version computes S in the LABEL-SORTED basis: the GEMM permutes its
// input rows by g_ord, so S_sorted[m1][m2] = f_{ord[m1]} . f_{ord[m2]} / tau.
// (Permuting rows+cols by one permutation preserves symmetry, and the loss is
// a sum over all pairs -> invariant.) The row kernel then reads contiguous
// rows (no gather), and the denom log-sum is fused directly into a lockstep
// merge-path pass.

#define NN 4096
#define DD 256

__device__ float g_S[(size_t)NN * NN];            // sorted-basis logits/tau
__device__ __align__(16) __nv_bfloat16 g_Fb[(size_t)NN * DD];
__device__ float g_ls[NN];                         // labels sorted ascending
__device__ int   g_ord[NN];
__device__ float g_partials[NN];

__device__ __forceinline__ float read_epoch(const void* p) {
    int ei = *(const int*)p;
    if (ei >= 0 && ei <= 1000000) return (float)ei;
    return *(const float*)p;
}

// ---------------- kernel 0: fp32 -> bf16 convert -----------------------------
__global__ void __launch_bounds__(256) convert_kernel(const float* __restrict__ F) {
    int base = (blockIdx.x * 256 + threadIdx.x) * 8;
    float4 v0 = *(const float4*)(F + base);
    float4 v1 = *(const float4*)(F + base + 4);
    __nv_bfloat162 b0 = __floats2bfloat162_rn(v0.x, v0.y);
    __nv_bfloat162 b1 = __floats2bfloat162_rn(v0.z, v0.w);
    __nv_bfloat162 b2 = __floats2bfloat162_rn(v1.x, v1.y);
    __nv_bfloat162 b3 = __floats2bfloat162_rn(v1.z, v1.w);
    uint4 packed;
    packed.x = *(uint32_t*)&b0; packed.y = *(uint32_t*)&b1;
    packed.z = *(uint32_t*)&b2; packed.w = *(uint32_t*)&b3;
    *(uint4*)(g_Fb + base) = packed;
}

// ---------------- kernel 1: labels + bitonic sort ----------------------------
__global__ void __launch_bounds__(1024) sort_kernel(
    const float* __restrict__ origin,
    const float* __restrict__ mean,
    const float* __restrict__ stdv)
{
    __shared__ float key[NN];
    __shared__ int   val[NN];
    int t = threadIdx.x;
    float mu = mean[0];
    float sd = stdv[0] + 1e-8f;
    for (int i = t; i < NN; i += 1024) {
        key[i] = (origin[i] - mu) / sd;
        val[i] = i;
    }
    __syncthreads();
    for (int k = 2; k <= NN; k <<= 1) {
        for (int j = k >> 1; j > 0; j >>= 1) {
            for (int i = t; i < NN; i += 1024) {
                int ixj = i ^ j;
                if (ixj > i) {
                    bool up = ((i & k) == 0);
                    float a = key[i], b = key[ixj];
                    if ((a > b) == up) {
                        key[i] = b; key[ixj] = a;
                        int tv = val[i]; val[i] = val[ixj]; val[ixj] = tv;
                    }
                }
            }
            __syncthreads();
        }
    }
    for (int i = t; i < NN; i += 1024) { g_ls[i] = key[i]; g_ord[i] = val[i]; }
}

// ---------------- kernel 2: bf16 HMMA GEMM, sorted basis ---------------------
#define ASTRIDE 40

__device__ __forceinline__ uint32_t sptr(const void* p) {
    return (uint32_t)__cvta_generic_to_shared(p);
}
__device__ __forceinline__ void ldsm4(uint32_t& r0, uint32_t& r1, uint32_t& r2,
                                      uint32_t& r3, uint32_t addr) {
    asm volatile("ldmatrix.sync.aligned.m8n8.x4.shared.b16 {%0,%1,%2,%3}, [%4];"
                 : "=r"(r0), "=r"(r1), "=r"(r2), "=r"(r3) : "r"(addr));
}
__device__ __forceinline__ void mma16816(float* c, uint32_t a0, uint32_t a1,
                                         uint32_t a2, uint32_t a3,
                                         uint32_t b0, uint32_t b1) {
    asm volatile(
        "mma.sync.aligned.m16n8k16.row.col.f32.bf16.bf16.f32 "
        "{%0,%1,%2,%3}, {%4,%5,%6,%7}, {%8,%9}, {%0,%1,%2,%3};"
        : "+f"(c[0]), "+f"(c[1]), "+f"(c[2]), "+f"(c[3])
        : "r"(a0), "r"(a1), "r"(a2), "r"(a3), "r"(b0), "r"(b1));
}

__global__ void __launch_bounds__(256) gemm_kernel(const void* __restrict__ epoch_ptr)
{
    __shared__ __align__(16) unsigned char smem_buf[2 * 128 * ASTRIDE * 2];
    __shared__ int s_ordA[128], s_ordB[128];
    __nv_bfloat16* sA = (__nv_bfloat16*)smem_buf;
    __nv_bfloat16* sB = sA + 128 * ASTRIDE;
    float* tr = (float*)smem_buf;

    int b = blockIdx.x;
    int bi = (int)((sqrtf(8.0f * b + 1.0f) - 1.0f) * 0.5f);
    while ((bi + 1) * (bi + 2) / 2 <= b) bi++;
    while (bi * (bi + 1) / 2 > b) bi--;
    int bj = b - bi * (bi + 1) / 2;
    int i0 = bi * 128, j0 = bj * 128;

    int t = threadIdx.x;
    int lane = t & 31, w = t >> 5;
    int warp_m = w & 1;
    int warp_n = w >> 1;

    if (t < 128) s_ordA[t] = g_ord[i0 + t];
    else         s_ordB[t - 128] = g_ord[j0 + (t - 128)];

    float epoch = read_epoch(epoch_ptr);
    float itau = 1.0f / (1.0f - 0.9f * epoch / 100.0f);

    float acc[4][4][4];
#pragma unroll
    for (int mb = 0; mb < 4; mb++)
#pragma unroll
        for (int nb = 0; nb < 4; nb++)
#pragma unroll
            for (int r = 0; r < 4; r++) acc[mb][nb][r] = 0.0f;

    __syncthreads();   // s_ord ready

    for (int kk = 0; kk < DD; kk += 32) {
#pragma unroll
        for (int s = 0; s < 2; s++) {
            int idx = t + s * 256;
            int r = idx >> 2, cg = idx & 3;
            uint4 va = *(const uint4*)(g_Fb + (size_t)s_ordA[r] * DD + kk + cg * 8);
            *(uint4*)(sA + r * ASTRIDE + cg * 8) = va;
            uint4 vb = *(const uint4*)(g_Fb + (size_t)s_ordB[r] * DD + kk + cg * 8);
            *(uint4*)(sB + r * ASTRIDE + cg * 8) = vb;
        }
        __syncthreads();

#pragma unroll
        for (int ks = 0; ks < 2; ks++) {
            int kb = ks * 16;
            uint32_t af[4][4];
#pragma unroll
            for (int mb = 0; mb < 4; mb++) {
                int row = warp_m * 64 + mb * 16 + (lane & 7) + ((lane >> 3) & 1) * 8;
                int col = kb + (lane >> 4) * 8;
                ldsm4(af[mb][0], af[mb][1], af[mb][2], af[mb][3],
                      sptr(sA + row * ASTRIDE + col));
            }
            uint32_t bf[2][4];
#pragma unroll
            for (int hb = 0; hb < 2; hb++) {
                int n = warp_n * 32 + hb * 16 + ((lane >> 4) & 1) * 8 + (lane & 7);
                int col = kb + ((lane >> 3) & 1) * 8;
                ldsm4(bf[hb][0], bf[hb][1], bf[hb][2], bf[hb][3],
                      sptr(sB + n * ASTRIDE + col));
            }
#pragma unroll
            for (int mb = 0; mb < 4; mb++)
#pragma unroll
                for (int nb = 0; nb < 4; nb++) {
                    int hb = nb >> 1, pr = nb & 1;
                    mma16816(acc[mb][nb], af[mb][0], af[mb][1], af[mb][2], af[mb][3],
                             bf[hb][pr * 2], bf[hb][pr * 2 + 1]);
                }
        }
        __syncthreads();
    }

#pragma unroll
    for (int mb = 0; mb < 4; mb++)
#pragma unroll
        for (int nb = 0; nb < 4; nb++)
#pragma unroll
            for (int r = 0; r < 4; r++) acc[mb][nb][r] *= itau;

#pragma unroll
    for (int mb = 0; mb < 4; mb++)
#pragma unroll
        for (int nb = 0; nb < 4; nb++) {
            int row = warp_m * 64 + mb * 16 + (lane >> 2);
            int col = warp_n * 32 + nb * 8 + (lane & 3) * 2;
            float2 v01 = make_float2(acc[mb][nb][0], acc[mb][nb][1]);
            float2 v23 = make_float2(acc[mb][nb][2], acc[mb][nb][3]);
            *(float2*)&g_S[(size_t)(i0 + row) * NN + j0 + col] = v01;
            *(float2*)&g_S[(size_t)(i0 + row + 8) * NN + j0 + col] = v23;
        }

    if (bi != bj) {
        __syncthreads();
#pragma unroll
        for (int c = 0; c < 4; c++) {
            if (warp_n == c) {
#pragma unroll
                for (int mb = 0; mb < 4; mb++)
#pragma unroll
                    for (int nb = 0; nb < 4; nb++) {
                        int row = warp_m * 64 + mb * 16 + (lane >> 2);
                        int cl = nb * 8 + (lane & 3) * 2;
                        tr[cl * 132 + row]           = acc[mb][nb][0];
                        tr[(cl + 1) * 132 + row]     = acc[mb][nb][1];
                        tr[cl * 132 + row + 8]       = acc[mb][nb][2];
                        tr[(cl + 1) * 132 + row + 8] = acc[mb][nb][3];
                    }
            }
            __syncthreads();
#pragma unroll
            for (int s = 0; s < 4; s++) {
                int q = t + s * 256;
                int cl = q >> 5, c4 = q & 31;
                float4 v = *(float4*)&tr[cl * 132 + c4 * 4];
                *(float4*)&g_S[(size_t)(j0 + c * 32 + cl) * NN + i0 + c4 * 4] = v;
            }
            __syncthreads();
        }
    }
}

// ---------------- kernel 3: per-row denom + partial loss ---------------------
// Sorted basis: row i's diagonal IS position i. d[m] = fl(ls[m] - ls[i]).
// L = [0,z0) (d<0), Z = [z0,z1) (d==0, contains i), R = [z1,NN).
// X[s] = -d[z0-1-s] asc, Y[r] = d[z1+r] asc. Merge-path (X-first on ties)
// yields rank for every position; denom + log computed INLINE in the merge.
#define ROW_THREADS 256
#define CH 16
#define PADN (NN + NN / 16)            // 4352
#define ROW_SMEM_FLOATS (2 * PADN + 256)
#define IDX(m) ((m) + ((m) >> 4))

__global__ void __launch_bounds__(ROW_THREADS) row_kernel()
{
    extern __shared__ float sm[];
    float* s_d   = sm;                  // sorted label diffs, padded
    float* s_p   = sm + PADN;           // exp -> inclusive scan, padded
    float* s_red = sm + 2 * PADN;

    const int i = blockIdx.x;
    const int t = threadIdx.x;
    const float* Srow = &g_S[(size_t)i * NN];
    const float li = g_ls[i];
    const float selfv = Srow[i];        // uniform broadcast load

    // contiguous float4 loads: diffs, exp, rowsum
    float rs = 0.0f;
    for (int m4 = t; m4 < NN / 4; m4 += ROW_THREADS) {
        int m = m4 * 4;
        int ix = IDX(m);                // m % 4 == 0 -> ix..ix+3 contiguous
        float4 l4 = *(const float4*)(g_ls + m);
        s_d[ix + 0] = l4.x - li;
        s_d[ix + 1] = l4.y - li;
        s_d[ix + 2] = l4.z - li;
        s_d[ix + 3] = l4.w - li;
        float4 v = *(const float4*)(Srow + m);
        rs += v.x + v.y + v.z + v.w;
        s_p[ix + 0] = __expf(v.x);
        s_p[ix + 1] = __expf(v.y);
        s_p[ix + 2] = __expf(v.z);
        s_p[ix + 3] = __expf(v.w);
    }
    __syncthreads();

    // inclusive scan of s_p (conflict-free: thread base stride 17)
    const int base = t * (CH + 1);
    float run = 0.0f;
#pragma unroll
    for (int q = 0; q < CH; q++) { run += s_p[base + q]; s_p[base + q] = run; }
    int lane = t & 31, warp = t >> 5;
    float v = run;
#pragma unroll
    for (int d = 1; d < 32; d <<= 1) {
        float u = __shfl_up_sync(0xFFFFFFFFu, v, d);
        if (lane >= d) v += u;
    }
    if (lane == 31) s_red[warp] = v;
    __syncthreads();
    if (warp == 0 && lane < 8) {
        float wv = s_red[lane];
#pragma unroll
        for (int d = 1; d < 8; d <<= 1) {
            float u = __shfl_up_sync(0xFFu, wv, d);
            if (lane >= d) wv += u;
        }
        s_red[lane] = wv;
    }
    __syncthreads();
    float off = (warp > 0 ? s_red[warp - 1] : 0.0f) + (v - run);
#pragma unroll
    for (int q = 0; q < CH; q++) s_p[base + q] += off;
    __syncthreads();

    const float T = s_p[IDX(NN - 1)];

    // z0 = first m with d >= 0 ; z1 = first m with d > 0
    int z0, z1;
    {
        int lo = 0, hi = NN;
        while (lo < hi) { int m = (lo + hi) >> 1; if (s_d[IDX(m)] < 0.0f) lo = m + 1; else hi = m; }
        z0 = lo;
        lo = 0; hi = NN;
        while (lo < hi) { int m = (lo + hi) >> 1; if (s_d[IDX(m)] <= 0.0f) lo = m + 1; else hi = m; }
        z1 = lo;
    }

    const float e_self  = __expf(selfv);
    const float log_tie = __logf(T - e_self);
    float logsum = 0.0f;
    if (t == 0) logsum = (float)(z1 - z0 - 1) * log_tie;   // tie positions != i

    // ---- fused merge-path + denom/log ----
    const int nx = z0, ny = NN - z1, n = nx + ny;
    {
        int k = t * CH;
        if (k < n) {
            int lo = max(0, k - ny), hi = min(k, nx);
            while (lo < hi) {
                int mid = (lo + hi) >> 1;
                int sy = k - mid;
                bool adv = (sy > 0) && (mid < nx) &&
                           (s_d[IDX(z1 + sy - 1)] >= -s_d[IDX(z0 - 1 - mid)]);
                if (adv) lo = mid + 1; else hi = mid;
            }
            int sx = lo, sy = k - lo;
            float xv = (sx < nx) ? -s_d[IDX(z0 - 1 - sx)] : __int_as_float(0x7F800000);
            float yv = (sy < ny) ?  s_d[IDX(z1 + sy)]     : __int_as_float(0x7F800000);
            int lim = min(CH, n - k);
            for (int g = 0; g < lim; g++) {
                if (xv <= yv) {
                    // left position q = z0-1-sx, dq = -xv < 0 (exact rank)
                    int q = z0 - 1 - sx;
                    float dq = -xv;
                    int lo2 = q + 1;                       // tie-walk (rare)
                    while (s_d[IDX(lo2)] <= dq) lo2++;
                    float denom = s_p[IDX(lo2 - 1)] + (T - s_p[IDX(z1 + sy - 1)]);
                    logsum += __logf(denom);
                    sx++;
                    xv = (sx < nx) ? -s_d[IDX(z0 - 1 - sx)] : __int_as_float(0x7F800000);
                } else {
                    // right position q = z1+sy, dq = yv > 0
                    int q = z1 + sy;
                    float dq = yv;
                    int r = q;                             // tie-walk (rare)
                    while (s_d[IDX(r - 1)] >= dq) r--;
                    int a = z0 - sx;
                    float left = (a > 0) ? s_p[IDX(a - 1)] : 0.0f;
                    logsum += __logf(left + (T - s_p[IDX(r - 1)]));
                    sy++;
                    yv = (sy < ny) ? s_d[IDX(z1 + sy)] : __int_as_float(0x7F800000);
                }
            }
        }
    }

    // reduce rs and logsum
    __syncthreads();
    s_red[t] = rs;
    __syncthreads();
    for (int s = ROW_THREADS / 2; s > 0; s >>= 1) {
        if (t < s) s_red[t] += s_red[t + s];
        __syncthreads();
    }
    float rowsum = s_red[0];
    __syncthreads();
    s_red[t] = logsum;
    __syncthreads();
    for (int s = ROW_THREADS / 2; s > 0; s >>= 1) {
        if (t < s) s_red[t] += s_red[t + s];
        __syncthreads();
    }
    if (t == 0) g_partials[i] = (rowsum - selfv) - s_red[0];
}

// ---------------- kernel 4: finalize ----------------------------------------
__global__ void __launch_bounds__(256) finalize_kernel(float* __restrict__ out)
{
    __shared__ double sh[256];
    int t = threadIdx.x;
    double a = 0.0;
    for (int i = t; i < NN; i += 256) a += (double)g_partials[i];
    sh[t] = a;
    __syncthreads();
    for (int s = 128; s > 0; s >>= 1) {
        if (t < s) sh[t] += sh[t + s];
        __syncthreads();
    }
    if (t == 0) out[0] = (float)(-sh[0] / ((double)NN * (double)(NN - 1)));
}

// ---------------- launch -----------------------------------------------------
extern "C" void kernel_launch(void* const* d_in, const int* in_sizes, int n_in,
                              void* d_out, int out_size)
{
    const float* F      = (const float*)d_in[0];
    const float* origin = (const float*)d_in[1];
    const float* mean   = (const float*)d_in[2];
    const float* stdv   = (const float*)d_in[3];
    const void*  epoch  = d_in[4];

    convert_kernel<<<(NN * DD) / (256 * 8), 256>>>(F);
    sort_kernel<<<1, 1024>>>(origin, mean, stdv);

    gemm_kernel<<<32 * 33 / 2, 256>>>(epoch);

    size_t smem = ROW_SMEM_FLOATS * sizeof(float);
    cudaFuncSetAttribute(row_kernel, cudaFuncAttributeMaxDynamicSharedMemorySize, (int)smem);
    row_kernel<<<NN, ROW_THREADS, smem>>>();

    finalize_kernel<<<1, 256>>>((float*)d_out);
}

// round 8
// speedup vs baseline: 2.4956x; 1.1552x over previous
#include <cuda_runtime.h>
#include <cuda_bf16.h>
#include <cstdint>

// RnCLoss: N=4096, D=256, scalar fp32 loss.
// loss = -1/(n(n-1)) * sum_{i != k} [ logits[i,k] - log(denom[i,k]) ]
//
// S computed in LABEL-SORTED basis (GEMM permutes input rows by g_ord).
// Row kernel: contiguous row loads, block scan of exp, then a lockstep
// merge over |d| where denom = PX + (T - PY) updates with ONE new LDS per
// consumed element (no searches, no tie-walks). Deterministic int64
// fixed-point atomic accumulation replaces the block-partials pass.

#define NN 4096
#define DD 256

__device__ float g_S[(size_t)NN * NN];            // sorted-basis logits/tau
__device__ __align__(16) __nv_bfloat16 g_Fb[(size_t)NN * DD];
__device__ float g_ls[NN];                         // labels sorted ascending
__device__ int   g_ord[NN];
__device__ long long g_acc;                        // fixed-point loss accum

#define ACC_SCALE 262144.0f                        // 2^18

__device__ __forceinline__ float read_epoch(const void* p) {
    int ei = *(const int*)p;
    if (ei >= 0 && ei <= 1000000) return (float)ei;
    return *(const float*)p;
}

// ---------------- kernel 0: fp32 -> bf16 convert -----------------------------
__global__ void __launch_bounds__(256) convert_kernel(const float* __restrict__ F) {
    int base = (blockIdx.x * 256 + threadIdx.x) * 8;
    float4 v0 = *(const float4*)(F + base);
    float4 v1 = *(const float4*)(F + base + 4);
    __nv_bfloat162 b0 = __floats2bfloat162_rn(v0.x, v0.y);
    __nv_bfloat162 b1 = __floats2bfloat162_rn(v0.z, v0.w);
    __nv_bfloat162 b2 = __floats2bfloat162_rn(v1.x, v1.y);
    __nv_bfloat162 b3 = __floats2bfloat162_rn(v1.z, v1.w);
    uint4 packed;
    packed.x = *(uint32_t*)&b0; packed.y = *(uint32_t*)&b1;
    packed.z = *(uint32_t*)&b2; packed.w = *(uint32_t*)&b3;
    *(uint4*)(g_Fb + base) = packed;
}

// ---------------- kernel 1: labels + bitonic sort (+ acc zero) ---------------
__global__ void __launch_bounds__(1024) sort_kernel(
    const float* __restrict__ origin,
    const float* __restrict__ mean,
    const float* __restrict__ stdv)
{
    __shared__ float key[NN];
    __shared__ int   val[NN];
    int t = threadIdx.x;
    if (t == 0) g_acc = 0;             // reset accumulator every launch/replay
    float mu = mean[0];
    float sd = stdv[0] + 1e-8f;
    for (int i = t; i < NN; i += 1024) {
        key[i] = (origin[i] - mu) / sd;
        val[i] = i;
    }
    __syncthreads();
    for (int k = 2; k <= NN; k <<= 1) {
        for (int j = k >> 1; j > 0; j >>= 1) {
            for (int i = t; i < NN; i += 1024) {
                int ixj = i ^ j;
                if (ixj > i) {
                    bool up = ((i & k) == 0);
                    float a = key[i], b = key[ixj];
                    if ((a > b) == up) {
                        key[i] = b; key[ixj] = a;
                        int tv = val[i]; val[i] = val[ixj]; val[ixj] = tv;
                    }
                }
            }
            __syncthreads();
        }
    }
    for (int i = t; i < NN; i += 1024) { g_ls[i] = key[i]; g_ord[i] = val[i]; }
}

// ---------------- kernel 2: bf16 HMMA GEMM, sorted basis ---------------------
#define ASTRIDE 40

__device__ __forceinline__ uint32_t sptr(const void* p) {
    return (uint32_t)__cvta_generic_to_shared(p);
}
__device__ __forceinline__ void ldsm4(uint32_t& r0, uint32_t& r1, uint32_t& r2,
                                      uint32_t& r3, uint32_t addr) {
    asm volatile("ldmatrix.sync.aligned.m8n8.x4.shared.b16 {%0,%1,%2,%3}, [%4];"
                 : "=r"(r0), "=r"(r1), "=r"(r2), "=r"(r3) : "r"(addr));
}
__device__ __forceinline__ void mma16816(float* c, uint32_t a0, uint32_t a1,
                                         uint32_t a2, uint32_t a3,
                                         uint32_t b0, uint32_t b1) {
    asm volatile(
        "mma.sync.aligned.m16n8k16.row.col.f32.bf16.bf16.f32 "
        "{%0,%1,%2,%3}, {%4,%5,%6,%7}, {%8,%9}, {%0,%1,%2,%3};"
        : "+f"(c[0]), "+f"(c[1]), "+f"(c[2]), "+f"(c[3])
        : "r"(a0), "r"(a1), "r"(a2), "r"(a3), "r"(b0), "r"(b1));
}

__global__ void __launch_bounds__(256) gemm_kernel(const void* __restrict__ epoch_ptr)
{
    __shared__ __align__(16) unsigned char smem_buf[2 * 128 * ASTRIDE * 2];
    __shared__ int s_ordA[128], s_ordB[128];
    __nv_bfloat16* sA = (__nv_bfloat16*)smem_buf;
    __nv_bfloat16* sB = sA + 128 * ASTRIDE;
    float* tr = (float*)smem_buf;

    int b = blockIdx.x;
    int bi = (int)((sqrtf(8.0f * b + 1.0f) - 1.0f) * 0.5f);
    while ((bi + 1) * (bi + 2) / 2 <= b) bi++;
    while (bi * (bi + 1) / 2 > b) bi--;
    int bj = b - bi * (bi + 1) / 2;
    int i0 = bi * 128, j0 = bj * 128;

    int t = threadIdx.x;
    int lane = t & 31, w = t >> 5;
    int warp_m = w & 1;
    int warp_n = w >> 1;

    if (t < 128) s_ordA[t] = g_ord[i0 + t];
    else         s_ordB[t - 128] = g_ord[j0 + (t - 128)];

    float epoch = read_epoch(epoch_ptr);
    float itau = 1.0f / (1.0f - 0.9f * epoch / 100.0f);

    float acc[4][4][4];
#pragma unroll
    for (int mb = 0; mb < 4; mb++)
#pragma unroll
        for (int nb = 0; nb < 4; nb++)
#pragma unroll
            for (int r = 0; r < 4; r++) acc[mb][nb][r] = 0.0f;

    __syncthreads();

    for (int kk = 0; kk < DD; kk += 32) {
#pragma unroll
        for (int s = 0; s < 2; s++) {
            int idx = t + s * 256;
            int r = idx >> 2, cg = idx & 3;
            uint4 va = *(const uint4*)(g_Fb + (size_t)s_ordA[r] * DD + kk + cg * 8);
            *(uint4*)(sA + r * ASTRIDE + cg * 8) = va;
            uint4 vb = *(const uint4*)(g_Fb + (size_t)s_ordB[r] * DD + kk + cg * 8);
            *(uint4*)(sB + r * ASTRIDE + cg * 8) = vb;
        }
        __syncthreads();

#pragma unroll
        for (int ks = 0; ks < 2; ks++) {
            int kb = ks * 16;
            uint32_t af[4][4];
#pragma unroll
            for (int mb = 0; mb < 4; mb++) {
                int row = warp_m * 64 + mb * 16 + (lane & 7) + ((lane >> 3) & 1) * 8;
                int col = kb + (lane >> 4) * 8;
                ldsm4(af[mb][0], af[mb][1], af[mb][2], af[mb][3],
                      sptr(sA + row * ASTRIDE + col));
            }
            uint32_t bf[2][4];
#pragma unroll
            for (int hb = 0; hb < 2; hb++) {
                int n = warp_n * 32 + hb * 16 + ((lane >> 4) & 1) * 8 + (lane & 7);
                int col = kb + ((lane >> 3) & 1) * 8;
                ldsm4(bf[hb][0], bf[hb][1], bf[hb][2], bf[hb][3],
                      sptr(sB + n * ASTRIDE + col));
            }
#pragma unroll
            for (int mb = 0; mb < 4; mb++)
#pragma unroll
                for (int nb = 0; nb < 4; nb++) {
                    int hb = nb >> 1, pr = nb & 1;
                    mma16816(acc[mb][nb], af[mb][0], af[mb][1], af[mb][2], af[mb][3],
                             bf[hb][pr * 2], bf[hb][pr * 2 + 1]);
                }
        }
        __syncthreads();
    }

#pragma unroll
    for (int mb = 0; mb < 4; mb++)
#pragma unroll
        for (int nb = 0; nb < 4; nb++)
#pragma unroll
            for (int r = 0; r < 4; r++) acc[mb][nb][r] *= itau;

#pragma unroll
    for (int mb = 0; mb < 4; mb++)
#pragma unroll
        for (int nb = 0; nb < 4; nb++) {
            int row = warp_m * 64 + mb * 16 + (lane >> 2);
            int col = warp_n * 32 + nb * 8 + (lane & 3) * 2;
            float2 v01 = make_float2(acc[mb][nb][0], acc[mb][nb][1]);
            float2 v23 = make_float2(acc[mb][nb][2], acc[mb][nb][3]);
            *(float2*)&g_S[(size_t)(i0 + row) * NN + j0 + col] = v01;
            *(float2*)&g_S[(size_t)(i0 + row + 8) * NN + j0 + col] = v23;
        }

    if (bi != bj) {
        __syncthreads();
#pragma unroll
        for (int c = 0; c < 4; c++) {
            if (warp_n == c) {
#pragma unroll
                for (int mb = 0; mb < 4; mb++)
#pragma unroll
                    for (int nb = 0; nb < 4; nb++) {
                        int row = warp_m * 64 + mb * 16 + (lane >> 2);
                        int cl = nb * 8 + (lane & 3) * 2;
                        tr[cl * 132 + row]           = acc[mb][nb][0];
                        tr[(cl + 1) * 132 + row]     = acc[mb][nb][1];
                        tr[cl * 132 + row + 8]       = acc[mb][nb][2];
                        tr[(cl + 1) * 132 + row + 8] = acc[mb][nb][3];
                    }
            }
            __syncthreads();
#pragma unroll
            for (int s = 0; s < 4; s++) {
                int q = t + s * 256;
                int cl = q >> 5, c4 = q & 31;
                float4 v = *(float4*)&tr[cl * 132 + c4 * 4];
                *(float4*)&g_S[(size_t)(j0 + c * 32 + cl) * NN + i0 + c4 * 4] = v;
            }
            __syncthreads();
        }
    }
}

// ---------------- kernel 3: per-row denom + loss (incremental merge) ---------
// L = [0,z0) (d<0), Z = [z0,z1) (d==0, contains i), R = [z1,NN).
// X[s] = -d[z0-1-s] asc, Y[r] = d[z1+r] asc.  At merge state (sx,sy), the
// element about to be consumed (either side) has
//     denom = P[z0-1-sx] + (T - P[z1+sy-1])
// PX/PY update with one LDS per consumed element.
#define ROW_THREADS 256
#define CH 16
#define PADN (NN + NN / 16)            // 4352
#define ROW_SMEM_FLOATS (2 * PADN + 512)
#define IDX(m) ((m) + ((m) >> 4))
#define FINF __int_as_float(0x7F800000)

__global__ void __launch_bounds__(ROW_THREADS) row_kernel()
{
    extern __shared__ float sm[];
    float* s_d    = sm;                 // sorted label diffs, padded
    float* s_p    = sm + PADN;          // exp -> inclusive scan, padded
    float* s_red  = sm + 2 * PADN;      // 256
    float* s_red2 = sm + 2 * PADN + 256;

    const int i = blockIdx.x;
    const int t = threadIdx.x;
    const float* Srow = &g_S[(size_t)i * NN];
    const float li = g_ls[i];
    const float selfv = Srow[i];

    float rs = 0.0f;
    for (int m4 = t; m4 < NN / 4; m4 += ROW_THREADS) {
        int m = m4 * 4;
        int ix = IDX(m);
        float4 l4 = *(const float4*)(g_ls + m);
        s_d[ix + 0] = l4.x - li;
        s_d[ix + 1] = l4.y - li;
        s_d[ix + 2] = l4.z - li;
        s_d[ix + 3] = l4.w - li;
        float4 v = *(const float4*)(Srow + m);
        rs += v.x + v.y + v.z + v.w;
        s_p[ix + 0] = __expf(v.x);
        s_p[ix + 1] = __expf(v.y);
        s_p[ix + 2] = __expf(v.z);
        s_p[ix + 3] = __expf(v.w);
    }
    __syncthreads();

    // inclusive scan of s_p (conflict-free: thread base stride 17)
    const int base = t * (CH + 1);
    float run = 0.0f;
#pragma unroll
    for (int q = 0; q < CH; q++) { run += s_p[base + q]; s_p[base + q] = run; }
    int lane = t & 31, warp = t >> 5;
    float v = run;
#pragma unroll
    for (int d = 1; d < 32; d <<= 1) {
        float u = __shfl_up_sync(0xFFFFFFFFu, v, d);
        if (lane >= d) v += u;
    }
    if (lane == 31) s_red[warp] = v;
    __syncthreads();
    if (warp == 0 && lane < 8) {
        float wv = s_red[lane];
#pragma unroll
        for (int d = 1; d < 8; d <<= 1) {
            float u = __shfl_up_sync(0xFFu, wv, d);
            if (lane >= d) wv += u;
        }
        s_red[lane] = wv;
    }
    __syncthreads();
    float off = (warp > 0 ? s_red[warp - 1] : 0.0f) + (v - run);
#pragma unroll
    for (int q = 0; q < CH; q++) s_p[base + q] += off;
    __syncthreads();

    const float T = s_p[IDX(NN - 1)];

    // z0 = first m with d >= 0 ; z1 = first m with d > 0
    int z0, z1;
    {
        int lo = 0, hi = NN;
        while (lo < hi) { int m = (lo + hi) >> 1; if (s_d[IDX(m)] < 0.0f) lo = m + 1; else hi = m; }
        z0 = lo;
        lo = 0; hi = NN;
        while (lo < hi) { int m = (lo + hi) >> 1; if (s_d[IDX(m)] <= 0.0f) lo = m + 1; else hi = m; }
        z1 = lo;
    }

    const float e_self  = __expf(selfv);
    const float log_tie = __logf(T - e_self);
    float logsum = 0.0f;
    if (t == 0) logsum = (float)(z1 - z0 - 1) * log_tie;

    // ---- fused merge + incremental denom ----
    const int nx = z0, ny = NN - z1, n = nx + ny;
    {
        int k = t * CH;
        if (k < n) {
            int lo = max(0, k - ny), hi = min(k, nx);
            while (lo < hi) {
                int mid = (lo + hi) >> 1;
                int sy = k - mid;
                bool adv = (sy > 0) && (mid < nx) &&
                           (s_d[IDX(z1 + sy - 1)] >= -s_d[IDX(z0 - 1 - mid)]);
                if (adv) lo = mid + 1; else hi = mid;
            }
            int sx = lo, sy = k - lo;
            int idxX = z0 - 1 - sx;        // head of X (may be -1)
            int idxY = z1 + sy;            // head of Y (may be NN)
            float xv = (idxX >= 0) ? -s_d[IDX(idxX)] : FINF;
            float PX = (idxX >= 0) ?  s_p[IDX(idxX)] : 0.0f;
            float yv = (idxY < NN) ?  s_d[IDX(idxY)] : FINF;
            float PY = s_p[IDX(idxY - 1)];            // idxY-1 >= z1-1 >= 0
            int lim = min(CH, n - k);
            for (int g = 0; g < lim; g++) {
                logsum += __logf(PX + (T - PY));
                if (xv <= yv) {
                    idxX--;
                    if (idxX >= 0) {
                        xv = -s_d[IDX(idxX)];
                        PX =  s_p[IDX(idxX)];
                    } else { xv = FINF; PX = 0.0f; }
                } else {
                    PY = s_p[IDX(idxY)];
                    idxY++;
                    yv = (idxY < NN) ? s_d[IDX(idxY)] : FINF;
                }
            }
        }
    }

    // single fused reduction of rs and logsum
    __syncthreads();
    s_red[t]  = rs;
    s_red2[t] = logsum;
    __syncthreads();
    for (int s = ROW_THREADS / 2; s > 0; s >>= 1) {
        if (t < s) { s_red[t] += s_red[t + s]; s_red2[t] += s_red2[t + s]; }
        __syncthreads();
    }
    if (t == 0) {
        float partial = (s_red[0] - selfv) - s_red2[0];
        long long q = (long long)llrintf(partial * ACC_SCALE);
        atomicAdd((unsigned long long*)&g_acc, (unsigned long long)q);
    }
}

// ---------------- kernel 4: finalize ----------------------------------------
__global__ void finalize_kernel(float* __restrict__ out)
{
    double s = (double)g_acc / (double)ACC_SCALE;
    out[0] = (float)(-s / ((double)NN * (double)(NN - 1)));
}

// ---------------- launch -----------------------------------------------------
extern "C" void kernel_launch(void* const* d_in, const int* in_sizes, int n_in,
                              void* d_out, int out_size)
{
    const float* F      = (const float*)d_in[0];
    const float* origin = (const float*)d_in[1];
    const float* mean   = (const float*)d_in[2];
    const float* stdv   = (const float*)d_in[3];
    const void*  epoch  = d_in[4];

    convert_kernel<<<(NN * DD) / (256 * 8), 256>>>(F);
    sort_kernel<<<1, 1024>>>(origin, mean, stdv);

    gemm_kernel<<<32 * 33 / 2, 256>>>(epoch);

    size_t smem = ROW_SMEM_FLOATS * sizeof(float);
    cudaFuncSetAttribute(row_kernel, cudaFuncAttributeMaxDynamicSharedMemorySize, (int)smem);
    row_kernel<<<NN, ROW_THREADS, smem>>>();

    finalize_kernel<<<1, 1>>>((float*)d_out);
}

// round 9
// speedup vs baseline: 2.6322x; 1.0547x over previous
#include <cuda_runtime.h>
#include <cuda_bf16.h>
#include <cstdint>

// RnCLoss: N=4096, D=256, scalar fp32 loss.
// loss = -1/(n(n-1)) * sum_{i != k} [ logits[i,k] - log(denom[i,k]) ]
//
// S computed in LABEL-SORTED basis (GEMM permutes input rows by g_ord, via
// cp.async double-buffered bf16 HMMA over lower-triangle tiles).
// Row kernel: contiguous row loads, block scan, then a lockstep merge over
// |d| with an INTERLEAVED (d, P) float2 smem layout -> one LDS.64 per
// consumed element. Deterministic int64 fixed-point atomic loss accumulation.

#define NN 4096
#define DD 256

__device__ float g_S[(size_t)NN * NN];            // sorted-basis logits/tau
__device__ __align__(16) __nv_bfloat16 g_Fb[(size_t)NN * DD];
__device__ float g_ls[NN];                         // labels sorted ascending
__device__ int   g_ord[NN];
__device__ long long g_acc;                        // fixed-point loss accum

#define ACC_SCALE 262144.0f                        // 2^18

__device__ __forceinline__ float read_epoch(const void* p) {
    int ei = *(const int*)p;
    if (ei >= 0 && ei <= 1000000) return (float)ei;
    return *(const float*)p;
}

// ---------------- kernel 0: fp32 -> bf16 convert -----------------------------
__global__ void __launch_bounds__(256) convert_kernel(const float* __restrict__ F) {
    int base = (blockIdx.x * 256 + threadIdx.x) * 8;
    float4 v0 = *(const float4*)(F + base);
    float4 v1 = *(const float4*)(F + base + 4);
    __nv_bfloat162 b0 = __floats2bfloat162_rn(v0.x, v0.y);
    __nv_bfloat162 b1 = __floats2bfloat162_rn(v0.z, v0.w);
    __nv_bfloat162 b2 = __floats2bfloat162_rn(v1.x, v1.y);
    __nv_bfloat162 b3 = __floats2bfloat162_rn(v1.z, v1.w);
    uint4 packed;
    packed.x = *(uint32_t*)&b0; packed.y = *(uint32_t*)&b1;
    packed.z = *(uint32_t*)&b2; packed.w = *(uint32_t*)&b3;
    *(uint4*)(g_Fb + base) = packed;
}

// ---------------- kernel 1: labels + bitonic sort (+ acc zero) ---------------
__global__ void __launch_bounds__(1024) sort_kernel(
    const float* __restrict__ origin,
    const float* __restrict__ mean,
    const float* __restrict__ stdv)
{
    __shared__ float key[NN];
    __shared__ int   val[NN];
    int t = threadIdx.x;
    if (t == 0) g_acc = 0;
    float mu = mean[0];
    float sd = stdv[0] + 1e-8f;
    for (int i = t; i < NN; i += 1024) {
        key[i] = (origin[i] - mu) / sd;
        val[i] = i;
    }
    __syncthreads();
    for (int k = 2; k <= NN; k <<= 1) {
        for (int j = k >> 1; j > 0; j >>= 1) {
            for (int i = t; i < NN; i += 1024) {
                int ixj = i ^ j;
                if (ixj > i) {
                    bool up = ((i & k) == 0);
                    float a = key[i], b = key[ixj];
                    if ((a > b) == up) {
                        key[i] = b; key[ixj] = a;
                        int tv = val[i]; val[i] = val[ixj]; val[ixj] = tv;
                    }
                }
            }
            __syncthreads();
        }
    }
    for (int i = t; i < NN; i += 1024) { g_ls[i] = key[i]; g_ord[i] = val[i]; }
}

// ---------------- kernel 2: bf16 HMMA GEMM, sorted basis, cp.async DB --------
#define ASTRIDE 40
#define BUF_BYTES (128 * ASTRIDE * 2 * 2)    // A+B per buffer = 20480 B

__device__ __forceinline__ uint32_t sptr(const void* p) {
    return (uint32_t)__cvta_generic_to_shared(p);
}
__device__ __forceinline__ void cp_async16(uint32_t dst, const void* src) {
    asm volatile("cp.async.cg.shared.global [%0], [%1], 16;" :: "r"(dst), "l"(src));
}
#define CP_COMMIT() asm volatile("cp.async.commit_group;")
#define CP_WAIT(n)  asm volatile("cp.async.wait_group %0;" :: "n"(n))

__device__ __forceinline__ void ldsm4(uint32_t& r0, uint32_t& r1, uint32_t& r2,
                                      uint32_t& r3, uint32_t addr) {
    asm volatile("ldmatrix.sync.aligned.m8n8.x4.shared.b16 {%0,%1,%2,%3}, [%4];"
                 : "=r"(r0), "=r"(r1), "=r"(r2), "=r"(r3) : "r"(addr));
}
__device__ __forceinline__ void mma16816(float* c, uint32_t a0, uint32_t a1,
                                         uint32_t a2, uint32_t a3,
                                         uint32_t b0, uint32_t b1) {
    asm volatile(
        "mma.sync.aligned.m16n8k16.row.col.f32.bf16.bf16.f32 "
        "{%0,%1,%2,%3}, {%4,%5,%6,%7}, {%8,%9}, {%0,%1,%2,%3};"
        : "+f"(c[0]), "+f"(c[1]), "+f"(c[2]), "+f"(c[3])
        : "r"(a0), "r"(a1), "r"(a2), "r"(a3), "r"(b0), "r"(b1));
}

__global__ void __launch_bounds__(256) gemm_kernel(const void* __restrict__ epoch_ptr)
{
    __shared__ __align__(16) unsigned char smem_buf[2 * BUF_BYTES];
    __shared__ int s_ordA[128], s_ordB[128];
    float* tr = (float*)smem_buf;

    int b = blockIdx.x;
    int bi = (int)((sqrtf(8.0f * b + 1.0f) - 1.0f) * 0.5f);
    while ((bi + 1) * (bi + 2) / 2 <= b) bi++;
    while (bi * (bi + 1) / 2 > b) bi--;
    int bj = b - bi * (bi + 1) / 2;
    int i0 = bi * 128, j0 = bj * 128;

    int t = threadIdx.x;
    int lane = t & 31, w = t >> 5;
    int warp_m = w & 1;
    int warp_n = w >> 1;

    if (t < 128) s_ordA[t] = g_ord[i0 + t];
    else         s_ordB[t - 128] = g_ord[j0 + (t - 128)];

    float epoch = read_epoch(epoch_ptr);
    float itau = 1.0f / (1.0f - 0.9f * epoch / 100.0f);

    float acc[4][4][4];
#pragma unroll
    for (int mb = 0; mb < 4; mb++)
#pragma unroll
        for (int nb = 0; nb < 4; nb++)
#pragma unroll
            for (int r = 0; r < 4; r++) acc[mb][nb][r] = 0.0f;

    __syncthreads();   // s_ord ready

    // loader task for this thread: 2 A-chunks + 2 B-chunks of 16 B
    int r0i = t >> 2, cg0 = t & 3;
    int r1i = (t + 256) >> 2, cg1 = (t + 256) & 3;

    auto issue = [&](int kk, int buf) {
        __nv_bfloat16* dA = (__nv_bfloat16*)(smem_buf + buf * BUF_BYTES);
        __nv_bfloat16* dB = dA + 128 * ASTRIDE;
        cp_async16(sptr(dA + r0i * ASTRIDE + cg0 * 8),
                   g_Fb + (size_t)s_ordA[r0i] * DD + kk + cg0 * 8);
        cp_async16(sptr(dB + r0i * ASTRIDE + cg0 * 8),
                   g_Fb + (size_t)s_ordB[r0i] * DD + kk + cg0 * 8);
        cp_async16(sptr(dA + r1i * ASTRIDE + cg1 * 8),
                   g_Fb + (size_t)s_ordA[r1i] * DD + kk + cg1 * 8);
        cp_async16(sptr(dB + r1i * ASTRIDE + cg1 * 8),
                   g_Fb + (size_t)s_ordB[r1i] * DD + kk + cg1 * 8);
        CP_COMMIT();
    };

    issue(0, 0);
    for (int j = 0; j < DD / 32; j++) {
        if (j + 1 < DD / 32) { issue((j + 1) * 32, (j + 1) & 1); CP_WAIT(1); }
        else                 { CP_WAIT(0); }
        __syncthreads();

        __nv_bfloat16* sA = (__nv_bfloat16*)(smem_buf + (j & 1) * BUF_BYTES);
        __nv_bfloat16* sB = sA + 128 * ASTRIDE;
#pragma unroll
        for (int ks = 0; ks < 2; ks++) {
            int kb = ks * 16;
            uint32_t af[4][4];
#pragma unroll
            for (int mb = 0; mb < 4; mb++) {
                int row = warp_m * 64 + mb * 16 + (lane & 7) + ((lane >> 3) & 1) * 8;
                int col = kb + (lane >> 4) * 8;
                ldsm4(af[mb][0], af[mb][1], af[mb][2], af[mb][3],
                      sptr(sA + row * ASTRIDE + col));
            }
            uint32_t bf[2][4];
#pragma unroll
            for (int hb = 0; hb < 2; hb++) {
                int n = warp_n * 32 + hb * 16 + ((lane >> 4) & 1) * 8 + (lane & 7);
                int col = kb + ((lane >> 3) & 1) * 8;
                ldsm4(bf[hb][0], bf[hb][1], bf[hb][2], bf[hb][3],
                      sptr(sB + n * ASTRIDE + col));
            }
#pragma unroll
            for (int mb = 0; mb < 4; mb++)
#pragma unroll
                for (int nb = 0; nb < 4; nb++) {
                    int hb = nb >> 1, pr = nb & 1;
                    mma16816(acc[mb][nb], af[mb][0], af[mb][1], af[mb][2], af[mb][3],
                             bf[hb][pr * 2], bf[hb][pr * 2 + 1]);
                }
        }
        __syncthreads();
    }

#pragma unroll
    for (int mb = 0; mb < 4; mb++)
#pragma unroll
        for (int nb = 0; nb < 4; nb++)
#pragma unroll
            for (int r = 0; r < 4; r++) acc[mb][nb][r] *= itau;

#pragma unroll
    for (int mb = 0; mb < 4; mb++)
#pragma unroll
        for (int nb = 0; nb < 4; nb++) {
            int row = warp_m * 64 + mb * 16 + (lane >> 2);
            int col = warp_n * 32 + nb * 8 + (lane & 3) * 2;
            float2 v01 = make_float2(acc[mb][nb][0], acc[mb][nb][1]);
            float2 v23 = make_float2(acc[mb][nb][2], acc[mb][nb][3]);
            *(float2*)&g_S[(size_t)(i0 + row) * NN + j0 + col] = v01;
            *(float2*)&g_S[(size_t)(i0 + row + 8) * NN + j0 + col] = v23;
        }

    if (bi != bj) {
        __syncthreads();
#pragma unroll
        for (int c = 0; c < 4; c++) {
            if (warp_n == c) {
#pragma unroll
                for (int mb = 0; mb < 4; mb++)
#pragma unroll
                    for (int nb = 0; nb < 4; nb++) {
                        int row = warp_m * 64 + mb * 16 + (lane >> 2);
                        int cl = nb * 8 + (lane & 3) * 2;
                        tr[cl * 132 + row]           = acc[mb][nb][0];
                        tr[(cl + 1) * 132 + row]     = acc[mb][nb][1];
                        tr[cl * 132 + row + 8]       = acc[mb][nb][2];
                        tr[(cl + 1) * 132 + row + 8] = acc[mb][nb][3];
                    }
            }
            __syncthreads();
#pragma unroll
            for (int s = 0; s < 4; s++) {
                int q = t + s * 256;
                int cl = q >> 5, c4 = q & 31;
                float4 v = *(float4*)&tr[cl * 132 + c4 * 4];
                *(float4*)&g_S[(size_t)(j0 + c * 32 + cl) * NN + i0 + c4 * 4] = v;
            }
            __syncthreads();
        }
    }
}

// ---------------- kernel 3: per-row denom + loss (interleaved merge) ---------
// dp[m] = (d[m], P[m]) interleaved: one LDS.64 per merge consume.
// L = [0,z0), Z = [z0,z1) (contains i), R = [z1,NN).
// denom at merge state = P[headX] + (T - P[consumed-1 of Y]).
#define ROW_THREADS 256
#define CH 16
#define PADN (NN + NN / 16)                // 4352 logical slots
#define ROW_SMEM_FLOATS (2 * PADN + 512)
#define IDX(m)  ((m) + ((m) >> 4))
#define DPX(m)  (2 * IDX(m))               // float index of d; +1 is P
#define FINF __int_as_float(0x7F800000)

__global__ void __launch_bounds__(ROW_THREADS) row_kernel()
{
    extern __shared__ float sm[];
    float* dp     = sm;                    // interleaved (d, P), padded
    float* s_red  = sm + 2 * PADN;
    float* s_red2 = sm + 2 * PADN + 256;

    const int i = blockIdx.x;
    const int t = threadIdx.x;
    const float* Srow = &g_S[(size_t)i * NN];
    const float li = g_ls[i];
    const float selfv = Srow[i];

    float rs = 0.0f;
    for (int m4 = t; m4 < NN / 4; m4 += ROW_THREADS) {
        int m = m4 * 4;
        int ix2 = DPX(m);                  // 4 consecutive (d,P) pairs
        float4 l4 = *(const float4*)(g_ls + m);
        float4 v  = *(const float4*)(Srow + m);
        rs += v.x + v.y + v.z + v.w;
        *(float2*)&dp[ix2 + 0] = make_float2(l4.x - li, __expf(v.x));
        *(float2*)&dp[ix2 + 2] = make_float2(l4.y - li, __expf(v.y));
        *(float2*)&dp[ix2 + 4] = make_float2(l4.z - li, __expf(v.z));
        *(float2*)&dp[ix2 + 6] = make_float2(l4.w - li, __expf(v.w));
    }
    __syncthreads();

    // inclusive scan of the P components (y of each pair)
    const int base2 = 34 * t;              // DPX(t*CH)
    float run = 0.0f;
#pragma unroll
    for (int q = 0; q < CH; q++) { run += dp[base2 + 2 * q + 1]; dp[base2 + 2 * q + 1] = run; }
    int lane = t & 31, warp = t >> 5;
    float v = run;
#pragma unroll
    for (int d = 1; d < 32; d <<= 1) {
        float u = __shfl_up_sync(0xFFFFFFFFu, v, d);
        if (lane >= d) v += u;
    }
    if (lane == 31) s_red[warp] = v;
    __syncthreads();
    if (warp == 0 && lane < 8) {
        float wv = s_red[lane];
#pragma unroll
        for (int d = 1; d < 8; d <<= 1) {
            float u = __shfl_up_sync(0xFFu, wv, d);
            if (lane >= d) wv += u;
        }
        s_red[lane] = wv;
    }
    __syncthreads();
    float off = (warp > 0 ? s_red[warp - 1] : 0.0f) + (v - run);
#pragma unroll
    for (int q = 0; q < CH; q++) dp[base2 + 2 * q + 1] += off;
    __syncthreads();

    const float T = dp[DPX(NN - 1) + 1];

    // z0 = first m with d >= 0 ; z1 = first m with d > 0
    int z0, z1;
    {
        int lo = 0, hi = NN;
        while (lo < hi) { int m = (lo + hi) >> 1; if (dp[DPX(m)] < 0.0f) lo = m + 1; else hi = m; }
        z0 = lo;
        lo = 0; hi = NN;
        while (lo < hi) { int m = (lo + hi) >> 1; if (dp[DPX(m)] <= 0.0f) lo = m + 1; else hi = m; }
        z1 = lo;
    }

    const float e_self  = __expf(selfv);
    const float log_tie = __logf(T - e_self);
    float logsum = 0.0f;
    if (t == 0) logsum = (float)(z1 - z0 - 1) * log_tie;

    // ---- fused merge + incremental denom (one LDS.64 per consume) ----
    const int nx = z0, ny = NN - z1, n = nx + ny;
    {
        int k = t * CH;
        if (k < n) {
            int lo = max(0, k - ny), hi = min(k, nx);
            while (lo < hi) {
                int mid = (lo + hi) >> 1;
                int sy = k - mid;
                bool adv = (sy > 0) && (mid < nx) &&
                           (dp[DPX(z1 + sy - 1)] >= -dp[DPX(z0 - 1 - mid)]);
                if (adv) lo = mid + 1; else hi = mid;
            }
            int sx = lo, sy = k - lo;
            int idxX = z0 - 1 - sx;        // head of X (may be -1)
            int idxY = z1 + sy;            // head of Y (may be NN)
            float xv, PX, yv, pyH;
            if (idxX >= 0) { float2 e = *(float2*)&dp[DPX(idxX)]; xv = -e.x; PX = e.y; }
            else           { xv = FINF; PX = 0.0f; }
            if (idxY < NN) { float2 e = *(float2*)&dp[DPX(idxY)]; yv = e.x; pyH = e.y; }
            else           { yv = FINF; pyH = 0.0f; }
            float TmPY = T - dp[DPX(idxY - 1) + 1];   // idxY-1 >= z1-1 >= 0
            int lim = min(CH, n - k);
            for (int g = 0; g < lim; g++) {
                logsum += __logf(PX + TmPY);
                if (xv <= yv) {
                    idxX--;
                    if (idxX >= 0) {
                        float2 e = *(float2*)&dp[DPX(idxX)];
                        xv = -e.x; PX = e.y;
                    } else { xv = FINF; PX = 0.0f; }
                } else {
                    TmPY = T - pyH;
                    idxY++;
                    if (idxY < NN) {
                        float2 e = *(float2*)&dp[DPX(idxY)];
                        yv = e.x; pyH = e.y;
                    } else yv = FINF;
                }
            }
        }
    }

    // fused reduction of rs and logsum
    __syncthreads();
    s_red[t]  = rs;
    s_red2[t] = logsum;
    __syncthreads();
    for (int s = ROW_THREADS / 2; s > 0; s >>= 1) {
        if (t < s) { s_red[t] += s_red[t + s]; s_red2[t] += s_red2[t + s]; }
        __syncthreads();
    }
    if (t == 0) {
        float partial = (s_red[0] - selfv) - s_red2[0];
        long long q = (long long)llrintf(partial * ACC_SCALE);
        atomicAdd((unsigned long long*)&g_acc, (unsigned long long)q);
    }
}

// ---------------- kernel 4: finalize ----------------------------------------
__global__ void finalize_kernel(float* __restrict__ out)
{
    double s = (double)g_acc / (double)ACC_SCALE;
    out[0] = (float)(-s / ((double)NN * (double)(NN - 1)));
}

// ---------------- launch -----------------------------------------------------
extern "C" void kernel_launch(void* const* d_in, const int* in_sizes, int n_in,
                              void* d_out, int out_size)
{
    const float* F      = (const float*)d_in[0];
    const float* origin = (const float*)d_in[1];
    const float* mean   = (const float*)d_in[2];
    const float* stdv   = (const float*)d_in[3];
    const void*  epoch  = d_in[4];

    convert_kernel<<<(NN * DD) / (256 * 8), 256>>>(F);
    sort_kernel<<<1, 1024>>>(origin, mean, stdv);

    gemm_kernel<<<32 * 33 / 2, 256>>>(epoch);

    size_t smem = ROW_SMEM_FLOATS * sizeof(float);
    cudaFuncSetAttribute(row_kernel, cudaFuncAttributeMaxDynamicSharedMemorySize, (int)smem);
    row_kernel<<<NN, ROW_THREADS, smem>>>();

    finalize_kernel<<<1, 1>>>((float*)d_out);
}

// round 11
// speedup vs baseline: 2.6339x; 1.0007x over previous
#include <cuda_runtime.h>
#include <cuda_bf16.h>
#include <cstdint>

// RnCLoss: N=4096, D=256, scalar fp32 loss.
// loss = -1/(n(n-1)) * sum_{i != k} [ logits[i,k] - log(denom[i,k]) ]
//
// S computed in LABEL-SORTED basis (GEMM permutes input rows by g_ord).
// Row kernel insight: in merged (|d|-ascending) order, denom_r = S_all - C_r
// where C_r is the exclusive prefix of exp values in merged order and
// S_all = T - Z_sum. So: merge-scatter e into merged order (sentinel-guarded
// lockstep merge, contiguous stores), register block-scan, log pass from
// registers. No position-order prefix array at all.

#define NN 4096
#define DD 256

__device__ float g_S[(size_t)NN * NN];            // sorted-basis logits/tau
__device__ __align__(16) __nv_bfloat16 g_Fb[(size_t)NN * DD];
__device__ float g_ls[NN];                         // labels sorted ascending
__device__ int   g_ord[NN];
__device__ long long g_acc;                        // fixed-point loss accum
__device__ unsigned  g_done;                       // completed row blocks

#define ACC_SCALE 262144.0f                        // 2^18
#define FINF  __int_as_float(0x7F800000)
#define FNINF __int_as_float(0xFF800000)

__device__ __forceinline__ float read_epoch(const void* p) {
    int ei = *(const int*)p;
    if (ei >= 0 && ei <= 1000000) return (float)ei;
    return *(const float*)p;
}

// ---------------- kernel 1: fused convert + sort -----------------------------
// block 0 (1024 thr): label sort + accumulator reset. blocks 1..128: bf16 cvt.
__global__ void __launch_bounds__(1024) prep_kernel(
    const float* __restrict__ F,
    const float* __restrict__ origin,
    const float* __restrict__ mean,
    const float* __restrict__ stdv)
{
    if (blockIdx.x > 0) {
        int base = ((blockIdx.x - 1) * 1024 + threadIdx.x) * 8;
        float4 v0 = *(const float4*)(F + base);
        float4 v1 = *(const float4*)(F + base + 4);
        __nv_bfloat162 b0 = __floats2bfloat162_rn(v0.x, v0.y);
        __nv_bfloat162 b1 = __floats2bfloat162_rn(v0.z, v0.w);
        __nv_bfloat162 b2 = __floats2bfloat162_rn(v1.x, v1.y);
        __nv_bfloat162 b3 = __floats2bfloat162_rn(v1.z, v1.w);
        uint4 packed;
        packed.x = *(uint32_t*)&b0; packed.y = *(uint32_t*)&b1;
        packed.z = *(uint32_t*)&b2; packed.w = *(uint32_t*)&b3;
        *(uint4*)(g_Fb + base) = packed;
        return;
    }
    __shared__ float key[NN];
    __shared__ int   val[NN];
    int t = threadIdx.x;
    if (t == 0) { g_acc = 0; g_done = 0u; }
    float mu = mean[0];
    float sd = stdv[0] + 1e-8f;
    for (int i = t; i < NN; i += 1024) {
        key[i] = (origin[i] - mu) / sd;
        val[i] = i;
    }
    __syncthreads();
    for (int k = 2; k <= NN; k <<= 1) {
        for (int j = k >> 1; j > 0; j >>= 1) {
            for (int i = t; i < NN; i += 1024) {
                int ixj = i ^ j;
                if (ixj > i) {
                    bool up = ((i & k) == 0);
                    float a = key[i], b = key[ixj];
                    if ((a > b) == up) {
                        key[i] = b; key[ixj] = a;
                        int tv = val[i]; val[i] = val[ixj]; val[ixj] = tv;
                    }
                }
            }
            __syncthreads();
        }
    }
    for (int i = t; i < NN; i += 1024) { g_ls[i] = key[i]; g_ord[i] = val[i]; }
}

// ---------------- kernel 2: bf16 HMMA GEMM, sorted basis, cp.async DB --------
#define ASTRIDE 40
#define BUF_BYTES (128 * ASTRIDE * 2 * 2)    // A+B per buffer = 20480 B

__device__ __forceinline__ uint32_t sptr(const void* p) {
    return (uint32_t)__cvta_generic_to_shared(p);
}
__device__ __forceinline__ void cp_async16(uint32_t dst, const void* src) {
    asm volatile("cp.async.cg.shared.global [%0], [%1], 16;" :: "r"(dst), "l"(src));
}
#define CP_COMMIT() asm volatile("cp.async.commit_group;")
#define CP_WAIT(n)  asm volatile("cp.async.wait_group %0;" :: "n"(n))

__device__ __forceinline__ void ldsm4(uint32_t& r0, uint32_t& r1, uint32_t& r2,
                                      uint32_t& r3, uint32_t addr) {
    asm volatile("ldmatrix.sync.aligned.m8n8.x4.shared.b16 {%0,%1,%2,%3}, [%4];"
                 : "=r"(r0), "=r"(r1), "=r"(r2), "=r"(r3) : "r"(addr));
}
__device__ __forceinline__ void mma16816(float* c, uint32_t a0, uint32_t a1,
                                         uint32_t a2, uint32_t a3,
                                         uint32_t b0, uint32_t b1) {
    asm volatile(
        "mma.sync.aligned.m16n8k16.row.col.f32.bf16.bf16.f32 "
        "{%0,%1,%2,%3}, {%4,%5,%6,%7}, {%8,%9}, {%0,%1,%2,%3};"
        : "+f"(c[0]), "+f"(c[1]), "+f"(c[2]), "+f"(c[3])
        : "r"(a0), "r"(a1), "r"(a2), "r"(a3), "r"(b0), "r"(b1));
}

__global__ void __launch_bounds__(256) gemm_kernel(const void* __restrict__ epoch_ptr)
{
    __shared__ __align__(16) unsigned char smem_buf[2 * BUF_BYTES];
    __shared__ int s_ordA[128], s_ordB[128];
    float* tr = (float*)smem_buf;

    int b = blockIdx.x;
    int bi = (int)((sqrtf(8.0f * b + 1.0f) - 1.0f) * 0.5f);
    while ((bi + 1) * (bi + 2) / 2 <= b) bi++;
    while (bi * (bi + 1) / 2 > b) bi--;
    int bj = b - bi * (bi + 1) / 2;
    int i0 = bi * 128, j0 = bj * 128;

    int t = threadIdx.x;
    int lane = t & 31, w = t >> 5;
    int warp_m = w & 1;
    int warp_n = w >> 1;

    if (t < 128) s_ordA[t] = g_ord[i0 + t];
    else         s_ordB[t - 128] = g_ord[j0 + (t - 128)];

    float epoch = read_epoch(epoch_ptr);
    float itau = 1.0f / (1.0f - 0.9f * epoch / 100.0f);

    float acc[4][4][4];
#pragma unroll
    for (int mb = 0; mb < 4; mb++)
#pragma unroll
        for (int nb = 0; nb < 4; nb++)
#pragma unroll
            for (int r = 0; r < 4; r++) acc[mb][nb][r] = 0.0f;

    __syncthreads();

    int r0i = t >> 2, cg0 = t & 3;
    int r1i = (t + 256) >> 2, cg1 = (t + 256) & 3;

    auto issue = [&](int kk, int buf) {
        __nv_bfloat16* dA = (__nv_bfloat16*)(smem_buf + buf * BUF_BYTES);
        __nv_bfloat16* dB = dA + 128 * ASTRIDE;
        cp_async16(sptr(dA + r0i * ASTRIDE + cg0 * 8),
                   g_Fb + (size_t)s_ordA[r0i] * DD + kk + cg0 * 8);
        cp_async16(sptr(dB + r0i * ASTRIDE + cg0 * 8),
                   g_Fb + (size_t)s_ordB[r0i] * DD + kk + cg0 * 8);
        cp_async16(sptr(dA + r1i * ASTRIDE + cg1 * 8),
                   g_Fb + (size_t)s_ordA[r1i] * DD + kk + cg1 * 8);
        cp_async16(sptr(dB + r1i * ASTRIDE + cg1 * 8),
                   g_Fb + (size_t)s_ordB[r1i] * DD + kk + cg1 * 8);
        CP_COMMIT();
    };

    issue(0, 0);
    for (int j = 0; j < DD / 32; j++) {
        if (j + 1 < DD / 32) { issue((j + 1) * 32, (j + 1) & 1); CP_WAIT(1); }
        else                 { CP_WAIT(0); }
        __syncthreads();

        __nv_bfloat16* sA = (__nv_bfloat16*)(smem_buf + (j & 1) * BUF_BYTES);
        __nv_bfloat16* sB = sA + 128 * ASTRIDE;
#pragma unroll
        for (int ks = 0; ks < 2; ks++) {
            int kb = ks * 16;
            uint32_t af[4][4];
#pragma unroll
            for (int mb = 0; mb < 4; mb++) {
                int row = warp_m * 64 + mb * 16 + (lane & 7) + ((lane >> 3) & 1) * 8;
                int col = kb + (lane >> 4) * 8;
                ldsm4(af[mb][0], af[mb][1], af[mb][2], af[mb][3],
                      sptr(sA + row * ASTRIDE + col));
            }
            uint32_t bf[2][4];
#pragma unroll
            for (int hb = 0; hb < 2; hb++) {
                int n = warp_n * 32 + hb * 16 + ((lane >> 4) & 1) * 8 + (lane & 7);
                int col = kb + ((lane >> 3) & 1) * 8;
                ldsm4(bf[hb][0], bf[hb][1], bf[hb][2], bf[hb][3],
                      sptr(sB + n * ASTRIDE + col));
            }
#pragma unroll
            for (int mb = 0; mb < 4; mb++)
#pragma unroll
                for (int nb = 0; nb < 4; nb++) {
                    int hb = nb >> 1, pr = nb & 1;
                    mma16816(acc[mb][nb], af[mb][0], af[mb][1], af[mb][2], af[mb][3],
                             bf[hb][pr * 2], bf[hb][pr * 2 + 1]);
                }
        }
        __syncthreads();
    }

#pragma unroll
    for (int mb = 0; mb < 4; mb++)
#pragma unroll
        for (int nb = 0; nb < 4; nb++)
#pragma unroll
            for (int r = 0; r < 4; r++) acc[mb][nb][r] *= itau;

#pragma unroll
    for (int mb = 0; mb < 4; mb++)
#pragma unroll
        for (int nb = 0; nb < 4; nb++) {
            int row = warp_m * 64 + mb * 16 + (lane >> 2);
            int col = warp_n * 32 + nb * 8 + (lane & 3) * 2;
            float2 v01 = make_float2(acc[mb][nb][0], acc[mb][nb][1]);
            float2 v23 = make_float2(acc[mb][nb][2], acc[mb][nb][3]);
            *(float2*)&g_S[(size_t)(i0 + row) * NN + j0 + col] = v01;
            *(float2*)&g_S[(size_t)(i0 + row + 8) * NN + j0 + col] = v23;
        }

    if (bi != bj) {
        __syncthreads();
#pragma unroll
        for (int c = 0; c < 4; c++) {
            if (warp_n == c) {
#pragma unroll
                for (int mb = 0; mb < 4; mb++)
#pragma unroll
                    for (int nb = 0; nb < 4; nb++) {
                        int row = warp_m * 64 + mb * 16 + (lane >> 2);
                        int cl = nb * 8 + (lane & 3) * 2;
                        tr[cl * 132 + row]           = acc[mb][nb][0];
                        tr[(cl + 1) * 132 + row]     = acc[mb][nb][1];
                        tr[cl * 132 + row + 8]       = acc[mb][nb][2];
                        tr[(cl + 1) * 132 + row + 8] = acc[mb][nb][3];
                    }
            }
            __syncthreads();
#pragma unroll
            for (int s = 0; s < 4; s++) {
                int q = t + s * 256;
                int cl = q >> 5, c4 = q & 31;
                float4 v = *(float4*)&tr[cl * 132 + c4 * 4];
                *(float4*)&g_S[(size_t)(j0 + c * 32 + cl) * NN + i0 + c4 * 4] = v;
            }
            __syncthreads();
        }
    }
}

// ---------------- kernel 3: per-row loss (merge-scatter + register scan) -----
// dp[m] = (d[m], e[m]) interleaved, sentinel pairs at m=-1 and m=NN.
// L = [0,z0), Z = [z0,z1) (contains i), R = [z1,NN). Merge X (left, |d| asc)
// vs Y (right) scattering e into merged order, then denom_r = S_all - C_r.
#define ROW_THREADS 256
#define CH 16
#define PADN (NN + NN / 16)                 // 4352
#define IDX(m)  ((m) + ((m) >> 4))
#define DPX(m)  (2 * IDX(m) + 4)            // dp float index of d; +1 is e
#define DP_FLOATS (2 * PADN + 12)
#define ROW_SMEM_FLOATS (DP_FLOATS + PADN + 512)

__global__ void __launch_bounds__(ROW_THREADS) row_kernel(float* __restrict__ out)
{
    extern __shared__ float sm[];
    float* dp     = sm;                     // interleaved (d, e), sentinel-padded
    float* mg     = sm + DP_FLOATS;         // merged e values
    float* s_red  = mg + PADN;
    float* s_red2 = s_red + 256;
    __shared__ float sh_Sall, sh_ltie;

    const int i = blockIdx.x;
    const int t = threadIdx.x;
    const float* Srow = &g_S[(size_t)i * NN];
    const float li = g_ls[i];
    const float selfv = Srow[i];

    if (t == 0) {
        dp[DPX(-1)]     = FNINF; dp[DPX(-1) + 1] = 0.0f;   // X sentinel
        dp[DPX(NN)]     = FINF;  dp[DPX(NN) + 1] = 0.0f;   // Y sentinel
    }

    float rs = 0.0f, re = 0.0f;
    for (int m4 = t; m4 < NN / 4; m4 += ROW_THREADS) {
        int m = m4 * 4;
        int ix2 = DPX(m);
        float4 l4 = *(const float4*)(g_ls + m);
        float4 v  = *(const float4*)(Srow + m);
        rs += v.x + v.y + v.z + v.w;
        float e0 = __expf(v.x), e1 = __expf(v.y);
        float e2 = __expf(v.z), e3 = __expf(v.w);
        re += e0 + e1 + e2 + e3;
        *(float2*)&dp[ix2 + 0] = make_float2(l4.x - li, e0);
        *(float2*)&dp[ix2 + 2] = make_float2(l4.y - li, e1);
        *(float2*)&dp[ix2 + 4] = make_float2(l4.z - li, e2);
        *(float2*)&dp[ix2 + 6] = make_float2(l4.w - li, e3);
    }
    __syncthreads();

    // fused block reduce: rs (logit rowsum) and re (T)
    s_red[t]  = rs;
    s_red2[t] = re;
    __syncthreads();
    for (int s = ROW_THREADS / 2; s > 0; s >>= 1) {
        if (t < s) { s_red[t] += s_red[t + s]; s_red2[t] += s_red2[t + s]; }
        __syncthreads();
    }
    const float rowsum = s_red[0];
    const float T      = s_red2[0];
    __syncthreads();                       // s_red free for reuse below

    // z0 = first m with d >= 0 ; z1 = first m with d > 0 (broadcast searches)
    int z0, z1;
    {
        int lo = 0, hi = NN;
        while (lo < hi) { int m = (lo + hi) >> 1; if (dp[DPX(m)] < 0.0f) lo = m + 1; else hi = m; }
        z0 = lo;
        lo = 0; hi = NN;
        while (lo < hi) { int m = (lo + hi) >> 1; if (dp[DPX(m)] <= 0.0f) lo = m + 1; else hi = m; }
        z1 = lo;
    }
    if (t == 0) {
        float zsum = 0.0f;
        for (int m = z0; m < z1; m++) zsum += dp[DPX(m) + 1];
        sh_Sall = T - zsum;
        sh_ltie = __logf(T - dp[DPX(i) + 1]);   // e_self
    }

    // ---- merge-path diagonal search + scatter e into merged order ----
    const int nx = z0, ny = NN - z1, n = nx + ny;
    const int k  = t * CH;
    const int mb = 17 * t;                  // IDX(k)
    if (k < n) {
        int lo = max(0, k - ny), hi = min(k, nx);
        while (lo < hi) {
            int mid = (lo + hi) >> 1;
            bool adv = (dp[DPX(z1 + (k - mid) - 1)] >= -dp[DPX(z0 - 1 - mid)]);
            if (adv) lo = mid + 1; else hi = mid;
        }
        int idxX = z0 - 1 - lo;             // >= -1 (sentinel)
        int idxY = z1 + (k - lo);           // <= NN (sentinel)
        float2 hx = *(float2*)&dp[DPX(idxX)];
        float2 hy = *(float2*)&dp[DPX(idxY)];
        float xv = -hx.x, eX = hx.y;
        float yv =  hy.x, eY = hy.y;
        int lim = min(CH, n - k);
#pragma unroll 4
        for (int g = 0; g < lim; g++) {
            bool tx = (xv <= yv);
            mg[mb + g] = tx ? eX : eY;
            if (tx) {
                idxX--;
                float2 h = *(float2*)&dp[DPX(idxX)];
                xv = -h.x; eX = h.y;
            } else {
                idxY++;
                float2 h = *(float2*)&dp[DPX(idxY)];
                yv = h.x; eY = h.y;
            }
        }
    }
    __syncthreads();

    // ---- register scan over merged e + log pass ----
    const int lim2 = max(0, min(CH, n - k));
    float e_loc[CH];
    float run = 0.0f;
#pragma unroll
    for (int q = 0; q < CH; q++) {
        float e = (q < lim2) ? mg[mb + q] : 0.0f;
        e_loc[q] = e;
        run += e;
    }
    int lane = t & 31, warp = t >> 5;
    float v = run;
#pragma unroll
    for (int d = 1; d < 32; d <<= 1) {
        float u = __shfl_up_sync(0xFFFFFFFFu, v, d);
        if (lane >= d) v += u;
    }
    if (lane == 31) s_red[warp] = v;
    __syncthreads();
    if (warp == 0 && lane < 8) {
        float wv = s_red[lane];
#pragma unroll
        for (int d = 1; d < 8; d <<= 1) {
            float u = __shfl_up_sync(0xFFu, wv, d);
            if (lane >= d) wv += u;
        }
        s_red[lane] = wv;
    }
    __syncthreads();
    float C = (warp > 0 ? s_red[warp - 1] : 0.0f) + (v - run);   // exclusive

    const float S_all = sh_Sall;
    float logsum = (t == 0) ? (float)(z1 - z0 - 1) * sh_ltie : 0.0f;
#pragma unroll 4
    for (int q = 0; q < lim2; q++) {
        logsum += __logf(S_all - C);
        C += e_loc[q];
    }

    // reduce logsum; deterministic fixed-point atomic; last block finalizes
    __syncthreads();
    s_red[t] = logsum;
    __syncthreads();
    for (int s = ROW_THREADS / 2; s > 0; s >>= 1) {
        if (t < s) s_red[t] += s_red[t + s];
        __syncthreads();
    }
    if (t == 0) {
        float partial = (rowsum - selfv) - s_red[0];
        long long q = (long long)llrintf(partial * ACC_SCALE);
        atomicAdd((unsigned long long*)&g_acc, (unsigned long long)q);
        __threadfence();
        unsigned old = atomicAdd(&g_done, 1u);
        if (old == NN - 1) {
            long long a = (long long)atomicAdd((unsigned long long*)&g_acc, 0ULL);
            double s = (double)a / (double)ACC_SCALE;
            out[0] = (float)(-s / ((double)NN * (double)(NN - 1)));
        }
    }
}

// ---------------- launch -----------------------------------------------------
extern "C" void kernel_launch(void* const* d_in, const int* in_sizes, int n_in,
                              void* d_out, int out_size)
{
    const float* F      = (const float*)d_in[0];
    const float* origin = (const float*)d_in[1];
    const float* mean   = (const float*)d_in[2];
    const float* stdv   = (const float*)d_in[3];
    const void*  epoch  = d_in[4];

    prep_kernel<<<1 + (NN * DD) / (1024 * 8), 1024>>>(F, origin, mean, stdv);

    gemm_kernel<<<32 * 33 / 2, 256>>>(epoch);

    size_t smem = ROW_SMEM_FLOATS * sizeof(float);
    cudaFuncSetAttribute(row_kernel, cudaFuncAttributeMaxDynamicSharedMemorySize, (int)smem);
    row_kernel<<<NN, ROW_THREADS, smem>>>((float*)d_out);
}

// round 12
// speedup vs baseline: 3.5315x; 1.3408x over previous
#include <cuda_runtime.h>
#include <cuda_bf16.h>
#include <cstdint>

// RnCLoss: N=4096, D=256, scalar fp32 loss.
// loss = -1/(n(n-1)) * sum_{i != k} [ logits[i,k] - log(denom[i,k]) ]
//
// S computed in LABEL-SORTED basis (GEMM permutes input rows by g_ord).
// Sorting is a fully-parallel COUNTING SORT (rank per element, 64 blocks)
// fused with the bf16 convert. Row kernel: merge-scatter of exp values into
// |d|-ascending order, register block-scan, denom_r = S_all - C_r, in-kernel
// finalize via fixed-point atomics + done counter.

#define NN 4096
#define DD 256

__device__ float g_S[(size_t)NN * NN];            // sorted-basis logits/tau
__device__ __align__(16) __nv_bfloat16 g_Fb[(size_t)NN * DD];
__device__ float g_ls[NN];                         // labels sorted ascending
__device__ int   g_ord[NN];
__device__ long long g_acc;                        // fixed-point loss accum
__device__ unsigned  g_done;                       // completed row blocks

#define ACC_SCALE 262144.0f                        // 2^18
#define FINF  __int_as_float(0x7F800000)
#define FNINF __int_as_float(0xFF800000)

__device__ __forceinline__ float read_epoch(const void* p) {
    int ei = *(const int*)p;
    if (ei >= 0 && ei <= 1000000) return (float)ei;
    return *(const float*)p;
}

// ---------------- kernel 1: fused convert + parallel counting sort -----------
// blocks 0..63: rank computation (64 i's per block, 16 sub-scanners per i).
// blocks 64..191: fp32 -> bf16 convert.
#define RANK_BLOCKS 64
#define I_PER_BLOCK (NN / RANK_BLOCKS)      // 64
#define SUBS 16
#define J_PER_SUB (NN / SUBS)               // 256

__global__ void __launch_bounds__(1024) prep_kernel(
    const float* __restrict__ F,
    const float* __restrict__ origin,
    const float* __restrict__ mean,
    const float* __restrict__ stdv)
{
    if (blockIdx.x >= RANK_BLOCKS) {
        int base = ((blockIdx.x - RANK_BLOCKS) * 1024 + threadIdx.x) * 8;
        float4 v0 = *(const float4*)(F + base);
        float4 v1 = *(const float4*)(F + base + 4);
        __nv_bfloat162 b0 = __floats2bfloat162_rn(v0.x, v0.y);
        __nv_bfloat162 b1 = __floats2bfloat162_rn(v0.z, v0.w);
        __nv_bfloat162 b2 = __floats2bfloat162_rn(v1.x, v1.y);
        __nv_bfloat162 b3 = __floats2bfloat162_rn(v1.z, v1.w);
        uint4 packed;
        packed.x = *(uint32_t*)&b0; packed.y = *(uint32_t*)&b1;
        packed.z = *(uint32_t*)&b2; packed.w = *(uint32_t*)&b3;
        *(uint4*)(g_Fb + base) = packed;
        return;
    }

    __shared__ float lab[NN];
    __shared__ int   part[SUBS][I_PER_BLOCK + 1];   // +1 pad vs conflicts
    const int t = threadIdx.x;
    if (blockIdx.x == 0 && t == 0) { g_acc = 0; g_done = 0u; }

    const float mu = mean[0];
    const float sd = stdv[0] + 1e-8f;
    for (int m = t; m < NN; m += 1024)
        lab[m] = (origin[m] - mu) / sd;
    __syncthreads();

    // thread (sub, ii): counts j in [sub*256, sub*256+256) against i = base+ii
    const int ii  = t & (I_PER_BLOCK - 1);          // 0..63
    const int sub = t >> 6;                         // 0..15
    const int i   = blockIdx.x * I_PER_BLOCK + ii;
    const float li = lab[i];

    int cnt = 0;
    const int j0 = sub * J_PER_SUB;
#pragma unroll 8
    for (int j = j0; j < j0 + J_PER_SUB; j++) {
        float lj = lab[j];                          // warp-broadcast LDS
        cnt += (lj < li) || (lj == li && j < i);
    }
    part[sub][ii] = cnt;
    __syncthreads();

    if (t < I_PER_BLOCK) {
        int rank = 0;
#pragma unroll
        for (int s = 0; s < SUBS; s++) rank += part[s][t];
        int myi = blockIdx.x * I_PER_BLOCK + t;
        g_ls[rank]  = lab[myi];
        g_ord[rank] = myi;
    }
}

// ---------------- kernel 2: bf16 HMMA GEMM, sorted basis, cp.async DB --------
#define ASTRIDE 40
#define BUF_BYTES (128 * ASTRIDE * 2 * 2)    // A+B per buffer = 20480 B

__device__ __forceinline__ uint32_t sptr(const void* p) {
    return (uint32_t)__cvta_generic_to_shared(p);
}
__device__ __forceinline__ void cp_async16(uint32_t dst, const void* src) {
    asm volatile("cp.async.cg.shared.global [%0], [%1], 16;" :: "r"(dst), "l"(src));
}
#define CP_COMMIT() asm volatile("cp.async.commit_group;")
#define CP_WAIT(n)  asm volatile("cp.async.wait_group %0;" :: "n"(n))

__device__ __forceinline__ void ldsm4(uint32_t& r0, uint32_t& r1, uint32_t& r2,
                                      uint32_t& r3, uint32_t addr) {
    asm volatile("ldmatrix.sync.aligned.m8n8.x4.shared.b16 {%0,%1,%2,%3}, [%4];"
                 : "=r"(r0), "=r"(r1), "=r"(r2), "=r"(r3) : "r"(addr));
}
__device__ __forceinline__ void mma16816(float* c, uint32_t a0, uint32_t a1,
                                         uint32_t a2, uint32_t a3,
                                         uint32_t b0, uint32_t b1) {
    asm volatile(
        "mma.sync.aligned.m16n8k16.row.col.f32.bf16.bf16.f32 "
        "{%0,%1,%2,%3}, {%4,%5,%6,%7}, {%8,%9}, {%0,%1,%2,%3};"
        : "+f"(c[0]), "+f"(c[1]), "+f"(c[2]), "+f"(c[3])
        : "r"(a0), "r"(a1), "r"(a2), "r"(a3), "r"(b0), "r"(b1));
}

__global__ void __launch_bounds__(256) gemm_kernel(const void* __restrict__ epoch_ptr)
{
    __shared__ __align__(16) unsigned char smem_buf[2 * BUF_BYTES];
    __shared__ int s_ordA[128], s_ordB[128];
    float* tr = (float*)smem_buf;

    int b = blockIdx.x;
    int bi = (int)((sqrtf(8.0f * b + 1.0f) - 1.0f) * 0.5f);
    while ((bi + 1) * (bi + 2) / 2 <= b) bi++;
    while (bi * (bi + 1) / 2 > b) bi--;
    int bj = b - bi * (bi + 1) / 2;
    int i0 = bi * 128, j0 = bj * 128;

    int t = threadIdx.x;
    int lane = t & 31, w = t >> 5;
    int warp_m = w & 1;
    int warp_n = w >> 1;

    if (t < 128) s_ordA[t] = g_ord[i0 + t];
    else         s_ordB[t - 128] = g_ord[j0 + (t - 128)];

    float epoch = read_epoch(epoch_ptr);
    float itau = 1.0f / (1.0f - 0.9f * epoch / 100.0f);

    float acc[4][4][4];
#pragma unroll
    for (int mb = 0; mb < 4; mb++)
#pragma unroll
        for (int nb = 0; nb < 4; nb++)
#pragma unroll
            for (int r = 0; r < 4; r++) acc[mb][nb][r] = 0.0f;

    __syncthreads();

    int r0i = t >> 2, cg0 = t & 3;
    int r1i = (t + 256) >> 2, cg1 = (t + 256) & 3;

    auto issue = [&](int kk, int buf) {
        __nv_bfloat16* dA = (__nv_bfloat16*)(smem_buf + buf * BUF_BYTES);
        __nv_bfloat16* dB = dA + 128 * ASTRIDE;
        cp_async16(sptr(dA + r0i * ASTRIDE + cg0 * 8),
                   g_Fb + (size_t)s_ordA[r0i] * DD + kk + cg0 * 8);
        cp_async16(sptr(dB + r0i * ASTRIDE + cg0 * 8),
                   g_Fb + (size_t)s_ordB[r0i] * DD + kk + cg0 * 8);
        cp_async16(sptr(dA + r1i * ASTRIDE + cg1 * 8),
                   g_Fb + (size_t)s_ordA[r1i] * DD + kk + cg1 * 8);
        cp_async16(sptr(dB + r1i * ASTRIDE + cg1 * 8),
                   g_Fb + (size_t)s_ordB[r1i] * DD + kk + cg1 * 8);
        CP_COMMIT();
    };

    issue(0, 0);
    for (int j = 0; j < DD / 32; j++) {
        if (j + 1 < DD / 32) { issue((j + 1) * 32, (j + 1) & 1); CP_WAIT(1); }
        else                 { CP_WAIT(0); }
        __syncthreads();

        __nv_bfloat16* sA = (__nv_bfloat16*)(smem_buf + (j & 1) * BUF_BYTES);
        __nv_bfloat16* sB = sA + 128 * ASTRIDE;
#pragma unroll
        for (int ks = 0; ks < 2; ks++) {
            int kb = ks * 16;
            uint32_t af[4][4];
#pragma unroll
            for (int mb = 0; mb < 4; mb++) {
                int row = warp_m * 64 + mb * 16 + (lane & 7) + ((lane >> 3) & 1) * 8;
                int col = kb + (lane >> 4) * 8;
                ldsm4(af[mb][0], af[mb][1], af[mb][2], af[mb][3],
                      sptr(sA + row * ASTRIDE + col));
            }
            uint32_t bf[2][4];
#pragma unroll
            for (int hb = 0; hb < 2; hb++) {
                int n = warp_n * 32 + hb * 16 + ((lane >> 4) & 1) * 8 + (lane & 7);
                int col = kb + ((lane >> 3) & 1) * 8;
                ldsm4(bf[hb][0], bf[hb][1], bf[hb][2], bf[hb][3],
                      sptr(sB + n * ASTRIDE + col));
            }
#pragma unroll
            for (int mb = 0; mb < 4; mb++)
#pragma unroll
                for (int nb = 0; nb < 4; nb++) {
                    int hb = nb >> 1, pr = nb & 1;
                    mma16816(acc[mb][nb], af[mb][0], af[mb][1], af[mb][2], af[mb][3],
                             bf[hb][pr * 2], bf[hb][pr * 2 + 1]);
                }
        }
        __syncthreads();
    }

#pragma unroll
    for (int mb = 0; mb < 4; mb++)
#pragma unroll
        for (int nb = 0; nb < 4; nb++)
#pragma unroll
            for (int r = 0; r < 4; r++) acc[mb][nb][r] *= itau;

#pragma unroll
    for (int mb = 0; mb < 4; mb++)
#pragma unroll
        for (int nb = 0; nb < 4; nb++) {
            int row = warp_m * 64 + mb * 16 + (lane >> 2);
            int col = warp_n * 32 + nb * 8 + (lane & 3) * 2;
            float2 v01 = make_float2(acc[mb][nb][0], acc[mb][nb][1]);
            float2 v23 = make_float2(acc[mb][nb][2], acc[mb][nb][3]);
            *(float2*)&g_S[(size_t)(i0 + row) * NN + j0 + col] = v01;
            *(float2*)&g_S[(size_t)(i0 + row + 8) * NN + j0 + col] = v23;
        }

    if (bi != bj) {
        __syncthreads();
#pragma unroll
        for (int c = 0; c < 4; c++) {
            if (warp_n == c) {
#pragma unroll
                for (int mb = 0; mb < 4; mb++)
#pragma unroll
                    for (int nb = 0; nb < 4; nb++) {
                        int row = warp_m * 64 + mb * 16 + (lane >> 2);
                        int cl = nb * 8 + (lane & 3) * 2;
                        tr[cl * 132 + row]           = acc[mb][nb][0];
                        tr[(cl + 1) * 132 + row]     = acc[mb][nb][1];
                        tr[cl * 132 + row + 8]       = acc[mb][nb][2];
                        tr[(cl + 1) * 132 + row + 8] = acc[mb][nb][3];
                    }
            }
            __syncthreads();
#pragma unroll
            for (int s = 0; s < 4; s++) {
                int q = t + s * 256;
                int cl = q >> 5, c4 = q & 31;
                float4 v = *(float4*)&tr[cl * 132 + c4 * 4];
                *(float4*)&g_S[(size_t)(j0 + c * 32 + cl) * NN + i0 + c4 * 4] = v;
            }
            __syncthreads();
        }
    }
}

// ---------------- kernel 3: per-row loss (merge-scatter + register scan) -----
// dp[m] = (d[m], e[m]) interleaved, sentinel pairs at m=-1 and m=NN.
// L = [0,z0), Z = [z0,z1) (contains i), R = [z1,NN). Merge X (left, |d| asc)
// vs Y (right) scattering e into merged order, then denom_r = S_all - C_r.
#define ROW_THREADS 256
#define CH 16
#define PADN (NN + NN / 16)                 // 4352
#define IDX(m)  ((m) + ((m) >> 4))
#define DPX(m)  (2 * IDX(m) + 4)            // dp float index of d; +1 is e
#define DP_FLOATS (2 * PADN + 12)
#define ROW_SMEM_FLOATS (DP_FLOATS + PADN + 512)

__global__ void __launch_bounds__(ROW_THREADS) row_kernel(float* __restrict__ out)
{
    extern __shared__ float sm[];
    float* dp     = sm;                     // interleaved (d, e), sentinel-padded
    float* mg     = sm + DP_FLOATS;         // merged e values
    float* s_red  = mg + PADN;
    float* s_red2 = s_red + 256;
    __shared__ float sh_Sall, sh_ltie;

    const int i = blockIdx.x;
    const int t = threadIdx.x;
    const float* Srow = &g_S[(size_t)i * NN];
    const float li = g_ls[i];
    const float selfv = Srow[i];

    if (t == 0) {
        dp[DPX(-1)]     = FNINF; dp[DPX(-1) + 1] = 0.0f;   // X sentinel
        dp[DPX(NN)]     = FINF;  dp[DPX(NN) + 1] = 0.0f;   // Y sentinel
    }

    float rs = 0.0f, re = 0.0f;
    for (int m4 = t; m4 < NN / 4; m4 += ROW_THREADS) {
        int m = m4 * 4;
        int ix2 = DPX(m);
        float4 l4 = *(const float4*)(g_ls + m);
        float4 v  = *(const float4*)(Srow + m);
        rs += v.x + v.y + v.z + v.w;
        float e0 = __expf(v.x), e1 = __expf(v.y);
        float e2 = __expf(v.z), e3 = __expf(v.w);
        re += e0 + e1 + e2 + e3;
        *(float2*)&dp[ix2 + 0] = make_float2(l4.x - li, e0);
        *(float2*)&dp[ix2 + 2] = make_float2(l4.y - li, e1);
        *(float2*)&dp[ix2 + 4] = make_float2(l4.z - li, e2);
        *(float2*)&dp[ix2 + 6] = make_float2(l4.w - li, e3);
    }
    __syncthreads();

    // fused block reduce: rs (logit rowsum) and re (T)
    s_red[t]  = rs;
    s_red2[t] = re;
    __syncthreads();
    for (int s = ROW_THREADS / 2; s > 0; s >>= 1) {
        if (t < s) { s_red[t] += s_red[t + s]; s_red2[t] += s_red2[t + s]; }
        __syncthreads();
    }
    const float rowsum = s_red[0];
    const float T      = s_red2[0];
    __syncthreads();                       // s_red free for reuse below

    // z0 = first m with d >= 0 ; z1 = first m with d > 0 (broadcast searches)
    int z0, z1;
    {
        int lo = 0, hi = NN;
        while (lo < hi) { int m = (lo + hi) >> 1; if (dp[DPX(m)] < 0.0f) lo = m + 1; else hi = m; }
        z0 = lo;
        lo = 0; hi = NN;
        while (lo < hi) { int m = (lo + hi) >> 1; if (dp[DPX(m)] <= 0.0f) lo = m + 1; else hi = m; }
        z1 = lo;
    }
    if (t == 0) {
        float zsum = 0.0f;
        for (int m = z0; m < z1; m++) zsum += dp[DPX(m) + 1];
        sh_Sall = T - zsum;
        sh_ltie = __logf(T - dp[DPX(i) + 1]);   // e_self
    }

    // ---- merge-path diagonal search + scatter e into merged order ----
    const int nx = z0, ny = NN - z1, n = nx + ny;
    const int k  = t * CH;
    const int mb = 17 * t;                  // IDX(k)
    if (k < n) {
        int lo = max(0, k - ny), hi = min(k, nx);
        while (lo < hi) {
            int mid = (lo + hi) >> 1;
            bool adv = (dp[DPX(z1 + (k - mid) - 1)] >= -dp[DPX(z0 - 1 - mid)]);
            if (adv) lo = mid + 1; else hi = mid;
        }
        int idxX = z0 - 1 - lo;             // >= -1 (sentinel)
        int idxY = z1 + (k - lo);           // <= NN (sentinel)
        float2 hx = *(float2*)&dp[DPX(idxX)];
        float2 hy = *(float2*)&dp[DPX(idxY)];
        float xv = -hx.x, eX = hx.y;
        float yv =  hy.x, eY = hy.y;
        int lim = min(CH, n - k);
#pragma unroll 4
        for (int g = 0; g < lim; g++) {
            bool tx = (xv <= yv);
            mg[mb + g] = tx ? eX : eY;
            if (tx) {
                idxX--;
                float2 h = *(float2*)&dp[DPX(idxX)];
                xv = -h.x; eX = h.y;
            } else {
                idxY++;
                float2 h = *(float2*)&dp[DPX(idxY)];
                yv = h.x; eY = h.y;
            }
        }
    }
    __syncthreads();

    // ---- register scan over merged e + log pass ----
    const int lim2 = max(0, min(CH, n - k));
    float e_loc[CH];
    float run = 0.0f;
#pragma unroll
    for (int q = 0; q < CH; q++) {
        float e = (q < lim2) ? mg[mb + q] : 0.0f;
        e_loc[q] = e;
        run += e;
    }
    int lane = t & 31, warp = t >> 5;
    float v = run;
#pragma unroll
    for (int d = 1; d < 32; d <<= 1) {
        float u = __shfl_up_sync(0xFFFFFFFFu, v, d);
        if (lane >= d) v += u;
    }
    if (lane == 31) s_red[warp] = v;
    __syncthreads();
    if (warp == 0 && lane < 8) {
        float wv = s_red[lane];
#pragma unroll
        for (int d = 1; d < 8; d <<= 1) {
            float u = __shfl_up_sync(0xFFu, wv, d);
            if (lane >= d) wv += u;
        }
        s_red[lane] = wv;
    }
    __syncthreads();
    float C = (warp > 0 ? s_red[warp - 1] : 0.0f) + (v - run);   // exclusive

    const float S_all = sh_Sall;
    float logsum = (t == 0) ? (float)(z1 - z0 - 1) * sh_ltie : 0.0f;
#pragma unroll 4
    for (int q = 0; q < lim2; q++) {
        logsum += __logf(S_all - C);
        C += e_loc[q];
    }

    // reduce logsum; deterministic fixed-point atomic; last block finalizes
    __syncthreads();
    s_red[t] = logsum;
    __syncthreads();
    for (int s = ROW_THREADS / 2; s > 0; s >>= 1) {
        if (t < s) s_red[t] += s_red[t + s];
        __syncthreads();
    }
    if (t == 0) {
        float partial = (rowsum - selfv) - s_red[0];
        long long q = (long long)llrintf(partial * ACC_SCALE);
        atomicAdd((unsigned long long*)&g_acc, (unsigned long long)q);
        __threadfence();
        unsigned old = atomicAdd(&g_done, 1u);
        if (old == NN - 1) {
            long long a = (long long)atomicAdd((unsigned long long*)&g_acc, 0ULL);
            double s = (double)a / (double)ACC_SCALE;
            out[0] = (float)(-s / ((double)NN * (double)(NN - 1)));
        }
    }
}

// ---------------- launch -----------------------------------------------------
extern "C" void kernel_launch(void* const* d_in, const int* in_sizes, int n_in,
                              void* d_out, int out_size)
{
    const float* F      = (const float*)d_in[0];
    const float* origin = (const float*)d_in[1];
    const float* mean   = (const float*)d_in[2];
    const float* stdv   = (const float*)d_in[3];
    const void*  epoch  = d_in[4];

    prep_kernel<<<RANK_BLOCKS + (NN * DD) / (1024 * 8), 1024>>>(F, origin, mean, stdv);

    gemm_kernel<<<32 * 33 / 2, 256>>>(epoch);

    size_t smem = ROW_SMEM_FLOATS * sizeof(float);
    cudaFuncSetAttribute(row_kernel, cudaFuncAttributeMaxDynamicSharedMemorySize, (int)smem);
    row_kernel<<<NN, ROW_THREADS, smem>>>((float*)d_out);
}

// round 17
// speedup vs baseline: 3.9058x; 1.1060x over previous
#include <cuda_runtime.h>
#include <cuda_bf16.h>
#include <cstdint>

// RnCLoss: N=4096, D=256, scalar fp32 loss.
// loss = -1/(n(n-1)) * sum_{i != k} [ logits[i,k] - log(denom[i,k]) ]
//
// NOTE: harness compiles for plain sm_100 (no 'a') -> tcgen05 unavailable;
// GEMM stays on mma.sync HMMA + cp.async double buffering.
// S computed in LABEL-SORTED basis (GEMM permutes input rows by g_ord).
// Row kernel: merge over |d| consuming exp values DIRECTLY INTO REGISTERS
// (no smem scatter/reload), register block-scan, denom_r = S_all - C_r,
// in-kernel finalize via fixed-point atomics + done counter.

#define NN 4096
#define DD 256

__device__ float g_S[(size_t)NN * NN];            // sorted-basis logits/tau
__device__ __align__(16) __nv_bfloat16 g_Fb[(size_t)NN * DD];
__device__ float g_ls[NN];                         // labels sorted ascending
__device__ int   g_ord[NN];
__device__ long long g_acc;                        // fixed-point loss accum
__device__ unsigned  g_done;                       // completed row blocks

#define ACC_SCALE 262144.0f                        // 2^18
#define FINF  __int_as_float(0x7F800000)
#define FNINF __int_as_float(0xFF800000)

__device__ __forceinline__ float read_epoch(const void* p) {
    int ei = *(const int*)p;
    if (ei >= 0 && ei <= 1000000) return (float)ei;
    return *(const float*)p;
}

// ---------------- kernel 1: fused convert + parallel counting sort -----------
#define RANK_BLOCKS 64
#define I_PER_BLOCK (NN / RANK_BLOCKS)      // 64
#define SUBS 16
#define J_PER_SUB (NN / SUBS)               // 256

__global__ void __launch_bounds__(1024) prep_kernel(
    const float* __restrict__ F,
    const float* __restrict__ origin,
    const float* __restrict__ mean,
    const float* __restrict__ stdv)
{
    if (blockIdx.x >= RANK_BLOCKS) {
        int base = ((blockIdx.x - RANK_BLOCKS) * 1024 + threadIdx.x) * 8;
        float4 v0 = *(const float4*)(F + base);
        float4 v1 = *(const float4*)(F + base + 4);
        __nv_bfloat162 b0 = __floats2bfloat162_rn(v0.x, v0.y);
        __nv_bfloat162 b1 = __floats2bfloat162_rn(v0.z, v0.w);
        __nv_bfloat162 b2 = __floats2bfloat162_rn(v1.x, v1.y);
        __nv_bfloat162 b3 = __floats2bfloat162_rn(v1.z, v1.w);
        uint4 packed;
        packed.x = *(uint32_t*)&b0; packed.y = *(uint32_t*)&b1;
        packed.z = *(uint32_t*)&b2; packed.w = *(uint32_t*)&b3;
        *(uint4*)(g_Fb + base) = packed;
        return;
    }

    __shared__ float lab[NN];
    __shared__ int   part[SUBS][I_PER_BLOCK + 1];
    const int t = threadIdx.x;
    if (blockIdx.x == 0 && t == 0) { g_acc = 0; g_done = 0u; }

    const float mu = mean[0];
    const float sd = stdv[0] + 1e-8f;
    for (int m = t; m < NN; m += 1024)
        lab[m] = (origin[m] - mu) / sd;
    __syncthreads();

    const int ii  = t & (I_PER_BLOCK - 1);
    const int sub = t >> 6;
    const int i   = blockIdx.x * I_PER_BLOCK + ii;
    const float li = lab[i];

    int cnt = 0;
    const int j0 = sub * J_PER_SUB;
#pragma unroll 8
    for (int j = j0; j < j0 + J_PER_SUB; j++) {
        float lj = lab[j];
        cnt += (lj < li) || (lj == li && j < i);
    }
    part[sub][ii] = cnt;
    __syncthreads();

    if (t < I_PER_BLOCK) {
        int rank = 0;
#pragma unroll
        for (int s = 0; s < SUBS; s++) rank += part[s][t];
        int myi = blockIdx.x * I_PER_BLOCK + t;
        g_ls[rank]  = lab[myi];
        g_ord[rank] = myi;
    }
}

// ---------------- kernel 2: bf16 HMMA GEMM, sorted basis, cp.async DB --------
#define ASTRIDE 40
#define BUF_BYTES (128 * ASTRIDE * 2 * 2)    // A+B per buffer = 20480 B

__device__ __forceinline__ uint32_t sptr(const void* p) {
    return (uint32_t)__cvta_generic_to_shared(p);
}
__device__ __forceinline__ void cp_async16(uint32_t dst, const void* src) {
    asm volatile("cp.async.cg.shared.global [%0], [%1], 16;" :: "r"(dst), "l"(src));
}
#define CP_COMMIT() asm volatile("cp.async.commit_group;")
#define CP_WAIT(n)  asm volatile("cp.async.wait_group %0;" :: "n"(n))

__device__ __forceinline__ void ldsm4(uint32_t& r0, uint32_t& r1, uint32_t& r2,
                                      uint32_t& r3, uint32_t addr) {
    asm volatile("ldmatrix.sync.aligned.m8n8.x4.shared.b16 {%0,%1,%2,%3}, [%4];"
                 : "=r"(r0), "=r"(r1), "=r"(r2), "=r"(r3) : "r"(addr));
}
__device__ __forceinline__ void mma16816(float* c, uint32_t a0, uint32_t a1,
                                         uint32_t a2, uint32_t a3,
                                         uint32_t b0, uint32_t b1) {
    asm volatile(
        "mma.sync.aligned.m16n8k16.row.col.f32.bf16.bf16.f32 "
        "{%0,%1,%2,%3}, {%4,%5,%6,%7}, {%8,%9}, {%0,%1,%2,%3};"
        : "+f"(c[0]), "+f"(c[1]), "+f"(c[2]), "+f"(c[3])
        : "r"(a0), "r"(a1), "r"(a2), "r"(a3), "r"(b0), "r"(b1));
}

__global__ void __launch_bounds__(256) gemm_kernel(const void* __restrict__ epoch_ptr)
{
    __shared__ __align__(16) unsigned char smem_buf[2 * BUF_BYTES];
    __shared__ int s_ordA[128], s_ordB[128];
    float* tr = (float*)smem_buf;

    int b = blockIdx.x;
    int bi = (int)((sqrtf(8.0f * b + 1.0f) - 1.0f) * 0.5f);
    while ((bi + 1) * (bi + 2) / 2 <= b) bi++;
    while (bi * (bi + 1) / 2 > b) bi--;
    int bj = b - bi * (bi + 1) / 2;
    int i0 = bi * 128, j0 = bj * 128;

    int t = threadIdx.x;
    int lane = t & 31, w = t >> 5;
    int warp_m = w & 1;
    int warp_n = w >> 1;

    if (t < 128) s_ordA[t] = g_ord[i0 + t];
    else         s_ordB[t - 128] = g_ord[j0 + (t - 128)];

    float epoch = read_epoch(epoch_ptr);
    float itau = 1.0f / (1.0f - 0.9f * epoch / 100.0f);

    float acc[4][4][4];
#pragma unroll
    for (int mb = 0; mb < 4; mb++)
#pragma unroll
        for (int nb = 0; nb < 4; nb++)
#pragma unroll
            for (int r = 0; r < 4; r++) acc[mb][nb][r] = 0.0f;

    __syncthreads();

    int r0i = t >> 2, cg0 = t & 3;
    int r1i = (t + 256) >> 2, cg1 = (t + 256) & 3;

    auto issue = [&](int kk, int buf) {
        __nv_bfloat16* dA = (__nv_bfloat16*)(smem_buf + buf * BUF_BYTES);
        __nv_bfloat16* dB = dA + 128 * ASTRIDE;
        cp_async16(sptr(dA + r0i * ASTRIDE + cg0 * 8),
                   g_Fb + (size_t)s_ordA[r0i] * DD + kk + cg0 * 8);
        cp_async16(sptr(dB + r0i * ASTRIDE + cg0 * 8),
                   g_Fb + (size_t)s_ordB[r0i] * DD + kk + cg0 * 8);
        cp_async16(sptr(dA + r1i * ASTRIDE + cg1 * 8),
                   g_Fb + (size_t)s_ordA[r1i] * DD + kk + cg1 * 8);
        cp_async16(sptr(dB + r1i * ASTRIDE + cg1 * 8),
                   g_Fb + (size_t)s_ordB[r1i] * DD + kk + cg1 * 8);
        CP_COMMIT();
    };

    issue(0, 0);
    for (int j = 0; j < DD / 32; j++) {
        if (j + 1 < DD / 32) { issue((j + 1) * 32, (j + 1) & 1); CP_WAIT(1); }
        else                 { CP_WAIT(0); }
        __syncthreads();

        __nv_bfloat16* sA = (__nv_bfloat16*)(smem_buf + (j & 1) * BUF_BYTES);
        __nv_bfloat16* sB = sA + 128 * ASTRIDE;
#pragma unroll
        for (int ks = 0; ks < 2; ks++) {
            int kb = ks * 16;
            uint32_t af[4][4];
#pragma unroll
            for (int mb = 0; mb < 4; mb++) {
                int row = warp_m * 64 + mb * 16 + (lane & 7) + ((lane >> 3) & 1) * 8;
                int col = kb + (lane >> 4) * 8;
                ldsm4(af[mb][0], af[mb][1], af[mb][2], af[mb][3],
                      sptr(sA + row * ASTRIDE + col));
            }
            uint32_t bf[2][4];
#pragma unroll
            for (int hb = 0; hb < 2; hb++) {
                int n = warp_n * 32 + hb * 16 + ((lane >> 4) & 1) * 8 + (lane & 7);
                int col = kb + ((lane >> 3) & 1) * 8;
                ldsm4(bf[hb][0], bf[hb][1], bf[hb][2], bf[hb][3],
                      sptr(sB + n * ASTRIDE + col));
            }
#pragma unroll
            for (int mb = 0; mb < 4; mb++)
#pragma unroll
                for (int nb = 0; nb < 4; nb++) {
                    int hb = nb >> 1, pr = nb & 1;
                    mma16816(acc[mb][nb], af[mb][0], af[mb][1], af[mb][2], af[mb][3],
                             bf[hb][pr * 2], bf[hb][pr * 2 + 1]);
                }
        }
        __syncthreads();
    }

#pragma unroll
    for (int mb = 0; mb < 4; mb++)
#pragma unroll
        for (int nb = 0; nb < 4; nb++)
#pragma unroll
            for (int r = 0; r < 4; r++) acc[mb][nb][r] *= itau;

#pragma unroll
    for (int mb = 0; mb < 4; mb++)
#pragma unroll
        for (int nb = 0; nb < 4; nb++) {
            int row = warp_m * 64 + mb * 16 + (lane >> 2);
            int col = warp_n * 32 + nb * 8 + (lane & 3) * 2;
            float2 v01 = make_float2(acc[mb][nb][0], acc[mb][nb][1]);
            float2 v23 = make_float2(acc[mb][nb][2], acc[mb][nb][3]);
            *(float2*)&g_S[(size_t)(i0 + row) * NN + j0 + col] = v01;
            *(float2*)&g_S[(size_t)(i0 + row + 8) * NN + j0 + col] = v23;
        }

    if (bi != bj) {
        __syncthreads();
#pragma unroll
        for (int c = 0; c < 4; c++) {
            if (warp_n == c) {
#pragma unroll
                for (int mb = 0; mb < 4; mb++)
#pragma unroll
                    for (int nb = 0; nb < 4; nb++) {
                        int row = warp_m * 64 + mb * 16 + (lane >> 2);
                        int cl = nb * 8 + (lane & 3) * 2;
                        tr[cl * 132 + row]           = acc[mb][nb][0];
                        tr[(cl + 1) * 132 + row]     = acc[mb][nb][1];
                        tr[cl * 132 + row + 8]       = acc[mb][nb][2];
                        tr[(cl + 1) * 132 + row + 8] = acc[mb][nb][3];
                    }
            }
            __syncthreads();
#pragma unroll
            for (int s = 0; s < 4; s++) {
                int q = t + s * 256;
                int cl = q >> 5, c4 = q & 31;
                float4 v = *(float4*)&tr[cl * 132 + c4 * 4];
                *(float4*)&g_S[(size_t)(j0 + c * 32 + cl) * NN + i0 + c4 * 4] = v;
            }
            __syncthreads();
        }
    }
}

// ---------------- kernel 3: per-row loss (register merge + register scan) ----
// dp[m] = (d[m], e[m]) interleaved, sentinel pairs at m=-1 and m=NN.
// L = [0,z0), Z = [z0,z1) (contains i), R = [z1,NN). Merge X (left, |d| asc)
// vs Y (right), consuming e DIRECTLY into registers e_loc[g]; then shuffle
// block-scan gives exclusive prefix C; denom_r = S_all - C_r.
#define ROW_THREADS 256
#define CH 16
#define PADN (NN + NN / 16)                 // 4352
#define IDX(m)  ((m) + ((m) >> 4))
#define DPX(m)  (2 * IDX(m) + 4)            // dp float index of d; +1 is e
#define DP_FLOATS (2 * PADN + 12)
#define ROW_SMEM_FLOATS (DP_FLOATS + 512)

__global__ void __launch_bounds__(ROW_THREADS) row_kernel(float* __restrict__ out)
{
    extern __shared__ float sm[];
    float* dp     = sm;                     // interleaved (d, e), sentinel-padded
    float* s_red  = sm + DP_FLOATS;
    float* s_red2 = s_red + 256;
    __shared__ float sh_Sall, sh_ltie;

    const int i = blockIdx.x;
    const int t = threadIdx.x;
    const float* Srow = &g_S[(size_t)i * NN];
    const float li = g_ls[i];
    const float selfv = Srow[i];

    if (t == 0) {
        dp[DPX(-1)]     = FNINF; dp[DPX(-1) + 1] = 0.0f;   // X sentinel
        dp[DPX(NN)]     = FINF;  dp[DPX(NN) + 1] = 0.0f;   // Y sentinel
    }

    float rs = 0.0f, re = 0.0f;
    for (int m4 = t; m4 < NN / 4; m4 += ROW_THREADS) {
        int m = m4 * 4;
        int ix2 = DPX(m);
        float4 l4 = *(const float4*)(g_ls + m);
        float4 v  = *(const float4*)(Srow + m);
        rs += v.x + v.y + v.z + v.w;
        float e0 = __expf(v.x), e1 = __expf(v.y);
        float e2 = __expf(v.z), e3 = __expf(v.w);
        re += e0 + e1 + e2 + e3;
        *(float2*)&dp[ix2 + 0] = make_float2(l4.x - li, e0);
        *(float2*)&dp[ix2 + 2] = make_float2(l4.y - li, e1);
        *(float2*)&dp[ix2 + 4] = make_float2(l4.z - li, e2);
        *(float2*)&dp[ix2 + 6] = make_float2(l4.w - li, e3);
    }
    __syncthreads();

    // fused block reduce: rs (logit rowsum) and re (T)
    s_red[t]  = rs;
    s_red2[t] = re;
    __syncthreads();
    for (int s = ROW_THREADS / 2; s > 0; s >>= 1) {
        if (t < s) { s_red[t] += s_red[t + s]; s_red2[t] += s_red2[t + s]; }
        __syncthreads();
    }
    const float rowsum = s_red[0];
    const float T      = s_red2[0];
    __syncthreads();

    // z0 = first m with d >= 0 ; z1 = first m with d > 0 (broadcast searches)
    int z0, z1;
    {
        int lo = 0, hi = NN;
        while (lo < hi) { int m = (lo + hi) >> 1; if (dp[DPX(m)] < 0.0f) lo = m + 1; else hi = m; }
        z0 = lo;
        lo = 0; hi = NN;
        while (lo < hi) { int m = (lo + hi) >> 1; if (dp[DPX(m)] <= 0.0f) lo = m + 1; else hi = m; }
        z1 = lo;
    }
    if (t == 0) {
        float zsum = 0.0f;
        for (int m = z0; m < z1; m++) zsum += dp[DPX(m) + 1];
        sh_Sall = T - zsum;
        sh_ltie = __logf(T - dp[DPX(i) + 1]);   // e_self
    }

    // ---- merge-path diagonal search + register consume ----
    const int nx = z0, ny = NN - z1, n = nx + ny;
    const int k  = t * CH;
    const int lim = (k < n) ? min(CH, n - k) : 0;
    float e_loc[CH];
    float run = 0.0f;
    if (lim > 0) {
        int lo = max(0, k - ny), hi = min(k, nx);
        while (lo < hi) {
            int mid = (lo + hi) >> 1;
            bool adv = (dp[DPX(z1 + (k - mid) - 1)] >= -dp[DPX(z0 - 1 - mid)]);
            if (adv) lo = mid + 1; else hi = mid;
        }
        int idxX = z0 - 1 - lo;             // >= -1 (sentinel)
        int idxY = z1 + (k - lo);           // <= NN (sentinel)
        float2 hx = *(float2*)&dp[DPX(idxX)];
        float2 hy = *(float2*)&dp[DPX(idxY)];
        float xv = -hx.x, eX = hx.y;
        float yv =  hy.x, eY = hy.y;
#pragma unroll
        for (int g = 0; g < CH; g++) {
            if (g < lim) {
                bool tx = (xv <= yv);
                float e = tx ? eX : eY;
                e_loc[g] = e;
                run += e;
                if (tx) {
                    idxX--;
                    float2 h = *(float2*)&dp[DPX(idxX)];
                    xv = -h.x; eX = h.y;
                } else {
                    idxY++;
                    float2 h = *(float2*)&dp[DPX(idxY)];
                    yv = h.x; eY = h.y;
                }
            } else e_loc[g] = 0.0f;
        }
    } else {
#pragma unroll
        for (int g = 0; g < CH; g++) e_loc[g] = 0.0f;
    }

    // ---- block scan of run -> exclusive prefix C ----
    __syncthreads();                        // s_red free
    int lane = t & 31, warp = t >> 5;
    float v = run;
#pragma unroll
    for (int d = 1; d < 32; d <<= 1) {
        float u = __shfl_up_sync(0xFFFFFFFFu, v, d);
        if (lane >= d) v += u;
    }
    if (lane == 31) s_red[warp] = v;
    __syncthreads();
    if (warp == 0 && lane < 8) {
        float wv = s_red[lane];
#pragma unroll
        for (int d = 1; d < 8; d <<= 1) {
            float u = __shfl_up_sync(0xFFu, wv, d);
            if (lane >= d) wv += u;
        }
        s_red[lane] = wv;
    }
    __syncthreads();
    float C = (warp > 0 ? s_red[warp - 1] : 0.0f) + (v - run);   // exclusive

    const float S_all = sh_Sall;
    float logsum = (t == 0) ? (float)(z1 - z0 - 1) * sh_ltie : 0.0f;
#pragma unroll
    for (int g = 0; g < CH; g++) {
        if (g < lim) {
            logsum += __logf(S_all - C);
            C += e_loc[g];
        }
    }

    // reduce logsum; deterministic fixed-point atomic; last block finalizes
    __syncthreads();
    s_red[t] = logsum;
    __syncthreads();
    for (int s = ROW_THREADS / 2; s > 0; s >>= 1) {
        if (t < s) s_red[t] += s_red[t + s];
        __syncthreads();
    }
    if (t == 0) {
        float partial = (rowsum - selfv) - s_red[0];
        long long q = (long long)llrintf(partial * ACC_SCALE);
        atomicAdd((unsigned long long*)&g_acc, (unsigned long long)q);
        __threadfence();
        unsigned old = atomicAdd(&g_done, 1u);
        if (old == NN - 1) {
            long long a = (long long)atomicAdd((unsigned long long*)&g_acc, 0ULL);
            double s = (double)a / (double)ACC_SCALE;
            out[0] = (float)(-s / ((double)NN * (double)(NN - 1)));
        }
    }
}

// ---------------- launch -----------------------------------------------------
extern "C" void kernel_launch(void* const* d_in, const int* in_sizes, int n_in,
                              void* d_out, int out_size)
{
    const float* F      = (const float*)d_in[0];
    const float* origin = (const float*)d_in[1];
    const float* mean   = (const float*)d_in[2];
    const float* stdv   = (const float*)d_in[3];
    const void*  epoch  = d_in[4];

    prep_kernel<<<RANK_BLOCKS + (NN * DD) / (1024 * 8), 1024>>>(F, origin, mean, stdv);

    gemm_kernel<<<32 * 33 / 2, 256>>>(epoch);

    size_t smem = ROW_SMEM_FLOATS * sizeof(float);
    cudaFuncSetAttribute(row_kernel, cudaFuncAttributeMaxDynamicSharedMemorySize, (int)smem);
    row_kernel<<<NN, ROW_THREADS, smem>>>((float*)d_out);
}